// round 4
// baseline (speedup 1.0000x reference)
#include <cuda_runtime.h>
#include <float.h>
#include <math.h>

#define NPTS 4096
#define NB 2
#define NN 8192
#define DD 64
#define KK 5
#define NKB (NPTS*KK)      /* 20480 flat (k-major) per batch */
#define EDGES (NB*NKB)     /* 40960 edges */

typedef unsigned long long u64;

/* ---------------- scratch (device globals; no allocation allowed) -------- */
__device__ float    g_xf1[NN*DD];
__device__ float    g_ge1[NN*DD];
__device__ float    g_ge2[NN*DD];
__device__ float    g_sq [NN];
__device__ int      g_idx1[NB*NKB];
__device__ int      g_idx2[NB*NKB];
__device__ float    g_A  [NN*DD];
__device__ float    g_B  [NN*DD];
__device__ unsigned g_acc[NN*DD];
__device__ float    g_x2 [NN*DD];
__device__ float    g_x3 [NN*DD];

/* ordered float<->uint key (monotone map, finite floats) */
__device__ __forceinline__ unsigned fkey(float f) {
    unsigned u = __float_as_uint(f);
    return u ^ ((unsigned)(((int)u) >> 31) | 0x80000000u);
}
__device__ __forceinline__ float fdec(unsigned u) {
    unsigned v = u ^ ((u & 0x80000000u) ? 0x80000000u : 0xFFFFFFFFu);
    return __uint_as_float(v);
}
#define NEG_MAX_KEY 0x00800000u   /* fkey(-FLT_MAX) */

/* packed f32x2 fma: d = a*b + c elementwise on two packed floats */
__device__ __forceinline__ u64 ffma2(u64 a, u64 b, u64 c) {
    u64 d;
    asm("fma.rn.f32x2 %0, %1, %2, %3;" : "=l"(d) : "l"(a), "l"(b), "l"(c));
    return d;
}
__device__ __forceinline__ float f2sum(u64 a) {
    unsigned lo = (unsigned)(a & 0xFFFFFFFFull);
    unsigned hi = (unsigned)(a >> 32);
    return __uint_as_float(lo) + __uint_as_float(hi);
}

/* cp.async helpers */
__device__ __forceinline__ void cp_async16(void* smem_dst, const void* gsrc) {
    unsigned s = (unsigned)__cvta_generic_to_shared(smem_dst);
    asm volatile("cp.async.ca.shared.global [%0], [%1], 16;" :: "r"(s), "l"(gsrc));
}
__device__ __forceinline__ void cp_commit() {
    asm volatile("cp.async.commit_group;" ::: "memory");
}
template<int N> __device__ __forceinline__ void cp_wait() {
    asm volatile("cp.async.wait_group %0;" :: "n"(N) : "memory");
}

/* ---------------- generic small GEMM: Y = act(X@W + b), 64 rows/block ---- */
template<int NCOL>
__global__ __launch_bounds__(256) void gemm_act(
    const float* __restrict__ X1, int k1,
    const float* __restrict__ X2, int k2,
    const float* __restrict__ W, const float* __restrict__ bias,
    float* __restrict__ Y, int act)
{
    constexpr int G  = NCOL / 4;
    constexpr int TY = 256 / G;
    constexpr int R  = 64 / TY;
    __shared__ float Ws[128 * NCOL];
    __shared__ float Xs[64 * 33];
    __shared__ float bs[NCOL];
    const int t = threadIdx.x;
    const int rowBase = blockIdx.x * 64;
    const int KD = k1 + k2;

    for (int f = t; f < KD * NCOL; f += 256) Ws[f] = W[f];
    if (t < NCOL) bs[t] = (bias != nullptr) ? bias[t] : 0.0f;

    const int tx = t % G, ty = t / G;
    float acc[R][4];
#pragma unroll
    for (int rr = 0; rr < R; rr++) { acc[rr][0]=0.f; acc[rr][1]=0.f; acc[rr][2]=0.f; acc[rr][3]=0.f; }

    for (int ko = 0; ko < KD; ko += 32) {
        const float* Xsrc; int stride, koff;
        if (ko < k1) { Xsrc = X1; stride = k1; koff = ko; }
        else         { Xsrc = X2; stride = k2; koff = ko - k1; }
        __syncthreads();
        for (int f = t; f < 64 * 32; f += 256) {
            int r = f >> 5, k = f & 31;
            Xs[r * 33 + k] = Xsrc[(rowBase + r) * stride + koff + k];
        }
        __syncthreads();
#pragma unroll
        for (int k = 0; k < 32; k++) {
            float4 w4 = *(const float4*)(Ws + (ko + k) * NCOL + tx * 4);
#pragma unroll
            for (int rr = 0; rr < R; rr++) {
                float xv = Xs[(ty + rr * TY) * 33 + k];
                acc[rr][0] += xv * w4.x; acc[rr][1] += xv * w4.y;
                acc[rr][2] += xv * w4.z; acc[rr][3] += xv * w4.w;
            }
        }
    }
#pragma unroll
    for (int rr = 0; rr < R; rr++) {
        int r = rowBase + ty + rr * TY;
        float4 o;
        o.x = acc[rr][0] + bs[tx*4+0];
        o.y = acc[rr][1] + bs[tx*4+1];
        o.z = acc[rr][2] + bs[tx*4+2];
        o.w = acc[rr][3] + bs[tx*4+3];
        if (act == 1) {          /* leaky relu 0.1 */
            o.x = o.x > 0.f ? o.x : 0.1f*o.x; o.y = o.y > 0.f ? o.y : 0.1f*o.y;
            o.z = o.z > 0.f ? o.z : 0.1f*o.z; o.w = o.w > 0.f ? o.w : 0.1f*o.w;
        } else if (act == 2) {   /* relu */
            o.x = fmaxf(o.x,0.f); o.y = fmaxf(o.y,0.f);
            o.z = fmaxf(o.z,0.f); o.w = fmaxf(o.w,0.f);
        }
        *(float4*)(Y + r * NCOL + tx * 4) = o;
    }
}

/* -------- fused EdgeConv GEMMs: A = X@(Wtop-Wbot)+bias, B = X@Wbot ------- */
__global__ __launch_bounds__(256) void gemm_ab(
    const float* __restrict__ X, const float* __restrict__ Wc,
    const float* __restrict__ bias, float* __restrict__ A, float* __restrict__ B)
{
    __shared__ float Ws[128 * 64];
    __shared__ float Xs[64 * 33];
    __shared__ float bs[64];
    const int t = threadIdx.x;
    const int rowBase = blockIdx.x * 64;
    for (int f = t; f < 128 * 64; f += 256) Ws[f] = Wc[f];
    if (t < 64) bs[t] = bias[t];

    const int tx = t % 16, ty = t / 16;        /* 16 col-groups x 16 rows */
    float aT[4][4], aB[4][4];
#pragma unroll
    for (int rr = 0; rr < 4; rr++)
#pragma unroll
        for (int c = 0; c < 4; c++) { aT[rr][c] = 0.f; aB[rr][c] = 0.f; }

    for (int ko = 0; ko < 64; ko += 32) {
        __syncthreads();
        for (int f = t; f < 64 * 32; f += 256) {
            int r = f >> 5, k = f & 31;
            Xs[r * 33 + k] = X[(rowBase + r) * 64 + ko + k];
        }
        __syncthreads();
#pragma unroll
        for (int k = 0; k < 32; k++) {
            float4 wt = *(const float4*)(Ws + (ko + k) * 64 + tx * 4);
            float4 wb = *(const float4*)(Ws + (64 + ko + k) * 64 + tx * 4);
#pragma unroll
            for (int rr = 0; rr < 4; rr++) {
                float xv = Xs[(ty + rr * 16) * 33 + k];
                aT[rr][0] = fmaf(xv, wt.x, aT[rr][0]); aT[rr][1] = fmaf(xv, wt.y, aT[rr][1]);
                aT[rr][2] = fmaf(xv, wt.z, aT[rr][2]); aT[rr][3] = fmaf(xv, wt.w, aT[rr][3]);
                aB[rr][0] = fmaf(xv, wb.x, aB[rr][0]); aB[rr][1] = fmaf(xv, wb.y, aB[rr][1]);
                aB[rr][2] = fmaf(xv, wb.z, aB[rr][2]); aB[rr][3] = fmaf(xv, wb.w, aB[rr][3]);
            }
        }
    }
#pragma unroll
    for (int rr = 0; rr < 4; rr++) {
        int r = rowBase + ty + rr * 16;
        float4 ao, bo;
        ao.x = aT[rr][0] - aB[rr][0] + bs[tx*4+0];
        ao.y = aT[rr][1] - aB[rr][1] + bs[tx*4+1];
        ao.z = aT[rr][2] - aB[rr][2] + bs[tx*4+2];
        ao.w = aT[rr][3] - aB[rr][3] + bs[tx*4+3];
        bo.x = aB[rr][0]; bo.y = aB[rr][1]; bo.z = aB[rr][2]; bo.w = aB[rr][3];
        *(float4*)(A + r * 64 + tx * 4) = ao;
        *(float4*)(B + r * 64 + tx * 4) = bo;
    }
}

/* ---------------- row sum of squares ------------------------------------- */
__global__ void sq_kernel(const float* __restrict__ ge, float* __restrict__ sq) {
    int r = blockIdx.x * blockDim.x + threadIdx.x;
    if (r >= NN) return;
    const float4* p = (const float4*)(ge + r * DD);
    float s0=0.f,s1=0.f,s2=0.f,s3=0.f;
#pragma unroll
    for (int d4 = 0; d4 < 16; d4++) {
        float4 v = p[d4];
        s0 += v.x*v.x; s1 += v.y*v.y; s2 += v.z*v.z; s3 += v.w*v.w;
    }
    sq[r] = (s0+s1)+(s2+s3);
}

/* ---------------- KNN: 1 query per lane, broadcast points, FFMA2 ---------
   Block: 32 queries (one per lane), 8 warps each own 8 point-rows per
   64-point tile (broadcast LDS). Query vector packed in 32 u64 registers.
   Inner product via fma.rn.f32x2 (2 scalar FMA per issue).
   Double-buffered tiles via cp.async. Single wave: 256 blocks, 2/SM.      */
__global__ __launch_bounds__(256, 2) void knn4_kernel(
    const float* __restrict__ ge, const float* __restrict__ sqg,
    int* __restrict__ idxflat)
{
    __shared__ float Ps[2][64 * 64];
    __shared__ float sqs[2][64];

    const int tid  = threadIdx.x;
    const int lane = tid & 31, warp = tid >> 5;
    const int qbase = blockIdx.x * 32;
    const int bb    = blockIdx.y;
    const float* gb  = ge + bb * NPTS * DD;
    const float* sqb = sqg + bb * NPTS;

    /* query vector as 32 packed f32x2 (register-pair aligned via 16B loads) */
    u64 qp[32];
    {
        const ulonglong2* qsrc = (const ulonglong2*)(gb + (qbase + lane) * DD);
#pragma unroll
        for (int d2 = 0; d2 < 16; d2++) {
            ulonglong2 v = qsrc[d2];
            qp[2*d2] = v.x; qp[2*d2+1] = v.y;
        }
    }
    const float sqj = sqb[qbase + lane];

    float tv[5]; int ti[5];
#pragma unroll
    for (int k = 0; k < 5; k++) { tv[k] = FLT_MAX; ti[k] = 0x7FFFFFFF; }

    /* prologue: tile 0 */
    for (int f = tid; f < 1024; f += 256)
        cp_async16(&Ps[0][(f >> 4) * 64 + (f & 15) * 4],
                   gb + (f >> 4) * DD + (f & 15) * 4);
    if (tid < 16) cp_async16(&sqs[0][tid * 4], sqb + tid * 4);
    cp_commit();

    for (int tt = 0; tt < 64; tt++) {
        if (tt < 63) {
            __syncthreads();            /* compute on buf[(tt+1)&1] finished */
            const float* src = gb + (tt + 1) * 64 * DD;
            float* dst = Ps[(tt + 1) & 1];
            for (int f = tid; f < 1024; f += 256)
                cp_async16(dst + (f >> 4) * 64 + (f & 15) * 4,
                           src + (f >> 4) * DD + (f & 15) * 4);
            if (tid < 16) cp_async16(&sqs[(tt + 1) & 1][tid * 4],
                                     sqb + (tt + 1) * 64 + tid * 4);
            cp_commit();
            cp_wait<1>();               /* tile tt landed */
        } else {
            cp_wait<0>();
        }
        __syncthreads();

        const float* P  = Ps[tt & 1];
        const float* SQ = sqs[tt & 1];
#pragma unroll
        for (int p = 0; p < 8; p++) {
            const int row = warp * 8 + p;
            const ulonglong2* pr = (const ulonglong2*)(P + row * 64);
            u64 a0 = 0ull, a1 = 0ull, a2 = 0ull, a3 = 0ull;
#pragma unroll
            for (int d2 = 0; d2 < 8; d2++) {
                ulonglong2 v0 = pr[2*d2];
                ulonglong2 v1 = pr[2*d2+1];
                a0 = ffma2(qp[4*d2+0], v0.x, a0);
                a1 = ffma2(qp[4*d2+1], v0.y, a1);
                a2 = ffma2(qp[4*d2+2], v1.x, a2);
                a3 = ffma2(qp[4*d2+3], v1.y, a3);
            }
            float dot  = (f2sum(a0) + f2sum(a1)) + (f2sum(a2) + f2sum(a3));
            float dist = fmaxf(fmaf(-2.0f, dot, sqj + SQ[row]), 0.0f);
            int   idx  = tt * 64 + row;
            if (dist < tv[4]) {
                tv[4] = dist; ti[4] = idx;
#pragma unroll
                for (int s2 = 4; s2 > 0; s2--) {
                    if (tv[s2] < tv[s2-1]) {
                        float fv = tv[s2]; tv[s2] = tv[s2-1]; tv[s2-1] = fv;
                        int  iv = ti[s2]; ti[s2] = ti[s2-1]; ti[s2-1] = iv;
                    }
                }
            }
        }
    }

    /* block merge: 8 warps x 5 candidates per query (lane). stride 41. */
    __syncthreads();
    float* cv = Ps[0];
    int*   ci = (int*)(Ps[0] + 32 * 41);
#pragma unroll
    for (int k = 0; k < 5; k++) {
        cv[lane * 41 + warp * 5 + k] = tv[k];
        ci[lane * 41 + warp * 5 + k] = ti[k];
    }
    __syncthreads();
    if (warp == 0) {
        float bv[5]; int bi[5];
#pragma unroll
        for (int k = 0; k < 5; k++) { bv[k] = FLT_MAX; bi[k] = 0x7FFFFFFF; }
        for (int e = 0; e < 40; e++) {
            float v = cv[lane * 41 + e];
            int   i = ci[lane * 41 + e];
            if (v < bv[4] || (v == bv[4] && i < bi[4])) {
                bv[4] = v; bi[4] = i;
#pragma unroll
                for (int s2 = 4; s2 > 0; s2--) {
                    if (bv[s2] < bv[s2-1] || (bv[s2] == bv[s2-1] && bi[s2] < bi[s2-1])) {
                        float fv = bv[s2]; bv[s2] = bv[s2-1]; bv[s2-1] = fv;
                        int  iv = bi[s2]; bi[s2] = bi[s2-1]; bi[s2-1] = iv;
                    }
                }
            }
        }
#pragma unroll
        for (int k = 0; k < 5; k++)
            idxflat[bb * NKB + k * NPTS + qbase + lane] = bi[k];
    }
}

/* ---------------- logprobs: lp[b,i,kk,layer] ----------------------------- */
__global__ void lp_kernel(const float* __restrict__ ge, const int* __restrict__ idxflat,
                          const float* __restrict__ tptr, float* __restrict__ outp, int layer)
{
    int gid = blockIdx.x * blockDim.x + threadIdx.x;
    if (gid >= NB * NKB) return;
    int bb = gid / NKB;
    int m  = gid - bb * NKB;
    float tval = fminf(fmaxf(tptr[0], -5.0f), 5.0f);
    float t = expf(tval);
    int nb  = idxflat[bb * NKB + m];
    int ctr = m / KK;
    int kk  = m - ctr * KK;
    const float4* pa = (const float4*)(ge + (bb * NPTS + nb) * DD);
    const float4* pb = (const float4*)(ge + (bb * NPTS + ctr) * DD);
    float s = 0.f;
#pragma unroll
    for (int d4 = 0; d4 < 16; d4++) {
        float4 a = pa[d4], b4 = pb[d4];
        float dx=a.x-b4.x, dy=a.y-b4.y, dz=a.z-b4.z, dw=a.w-b4.w;
        s += dx*dx + dy*dy + dz*dz + dw*dw;
    }
    outp[((bb * NPTS + ctr) * KK + kk) * 2 + layer] = -s * t;
}

/* ---------------- scatter-max edge conv --------------------------------- */
__global__ void init_acc_kernel(unsigned* __restrict__ acc) {
    int i = blockIdx.x * blockDim.x + threadIdx.x;
    if (i < NN * DD) acc[i] = NEG_MAX_KEY;
}

__global__ void scatter_kernel(const int* __restrict__ idxflat,
                               const float* __restrict__ A, const float* __restrict__ B,
                               unsigned* __restrict__ acc)
{
    int gid = blockIdx.x * blockDim.x + threadIdx.x;
    if (gid >= EDGES * 16) return;
    int q  = gid >> 4;
    int cg = gid & 15;
    int mq = q >> 2;
    int bb = (q >> 1) & 1;
    int c  = q & 1;
    int m_s = mq;
    int m_d = mq + NKB / 2;
    int srcv = (c == 0) ? idxflat[bb * NKB + m_s] : (m_s / KK);
    int dstv = (c == 0) ? idxflat[bb * NKB + m_d] : (m_d / KK);
    srcv += bb * NPTS;
    dstv += bb * NPTS;
    float4 av = ((const float4*)A)[dstv * 16 + cg];
    float4 bv = ((const float4*)B)[srcv * 16 + cg];
    unsigned* base = acc + dstv * DD + cg * 4;
    atomicMax(base + 0, fkey(av.x + bv.x));
    atomicMax(base + 1, fkey(av.y + bv.y));
    atomicMax(base + 2, fkey(av.z + bv.z));
    atomicMax(base + 3, fkey(av.w + bv.w));
}

__global__ void decode_relu_kernel(const unsigned* __restrict__ acc, float* __restrict__ y) {
    int i = blockIdx.x * blockDim.x + threadIdx.x;
    if (i < NN * DD) y[i] = fmaxf(fdec(acc[i]), 0.0f);
}

/* ---------------- fused head: lrelu(x@Wf1+b)@Wf2+b ----------------------- */
__global__ __launch_bounds__(128) void head_kernel(
    const float* __restrict__ x3,
    const float* __restrict__ Wf1, const float* __restrict__ bf1,
    const float* __restrict__ Wf2, const float* __restrict__ bf2,
    float* __restrict__ out)
{
    __shared__ float w1[64 * 32];
    __shared__ float w2[32 * 8];
    __shared__ float b1s[32], b2s[8];
    int t = threadIdx.x;
    for (int f = t; f < 2048; f += 128) w1[f] = Wf1[f];
    for (int f = t; f < 256;  f += 128) w2[f] = Wf2[f];
    if (t < 32) b1s[t] = bf1[t];
    if (t < 8)  b2s[t] = bf2[t];
    __syncthreads();
    int r = blockIdx.x * 128 + t;
    if (r >= NN) return;
    float xr[64];
#pragma unroll
    for (int d4 = 0; d4 < 16; d4++) {
        float4 v = ((const float4*)(x3 + r * DD))[d4];
        xr[d4*4+0]=v.x; xr[d4*4+1]=v.y; xr[d4*4+2]=v.z; xr[d4*4+3]=v.w;
    }
    float o[8];
#pragma unroll
    for (int k = 0; k < 8; k++) o[k] = b2s[k];
    for (int jj = 0; jj < 32; jj++) {
        float h0=0.f,h1=0.f,h2=0.f,h3=0.f;
#pragma unroll
        for (int k = 0; k < 64; k += 4) {
            h0 += xr[k+0] * w1[(k+0)*32 + jj];
            h1 += xr[k+1] * w1[(k+1)*32 + jj];
            h2 += xr[k+2] * w1[(k+2)*32 + jj];
            h3 += xr[k+3] * w1[(k+3)*32 + jj];
        }
        float h = ((h0+h1)+(h2+h3)) + b1s[jj];
        h = h > 0.f ? h : 0.1f * h;
#pragma unroll
        for (int k = 0; k < 8; k++) o[k] += h * w2[jj*8 + k];
    }
#pragma unroll
    for (int k = 0; k < 8; k++) out[r * 8 + k] = o[k];
}

/* ---------------- launch ------------------------------------------------- */
extern "C" void kernel_launch(void* const* d_in, const int* in_sizes, int n_in,
                              void* d_out, int out_size)
{
    const float* x     = (const float*)d_in[0];
    const float* W_pre = (const float*)d_in[1];
    const float* b_pre = (const float*)d_in[2];
    const float* W_d1  = (const float*)d_in[3];
    const float* b_d1  = (const float*)d_in[4];
    const float* t1    = (const float*)d_in[5];
    const float* W_c1  = (const float*)d_in[6];
    const float* b_c1  = (const float*)d_in[7];
    const float* W_d2  = (const float*)d_in[8];
    const float* b_d2  = (const float*)d_in[9];
    const float* t2    = (const float*)d_in[10];
    const float* W_c2  = (const float*)d_in[11];
    const float* b_c2  = (const float*)d_in[12];
    const float* W_f1  = (const float*)d_in[13];
    const float* b_f1  = (const float*)d_in[14];
    const float* W_f2  = (const float*)d_in[15];
    const float* b_f2  = (const float*)d_in[16];

    float* out = (float*)d_out;            /* [2,4096,8] = 65536 floats   */
    float* lp  = out + NN * 8;             /* [2,4096,5,2] = 81920 floats */

    float *p_xf1, *p_ge1, *p_ge2, *p_sq, *p_A, *p_B, *p_x2, *p_x3;
    int *p_idx1, *p_idx2;
    unsigned *p_acc;
    cudaGetSymbolAddress((void**)&p_xf1,  g_xf1);
    cudaGetSymbolAddress((void**)&p_ge1,  g_ge1);
    cudaGetSymbolAddress((void**)&p_ge2,  g_ge2);
    cudaGetSymbolAddress((void**)&p_sq,   g_sq);
    cudaGetSymbolAddress((void**)&p_idx1, g_idx1);
    cudaGetSymbolAddress((void**)&p_idx2, g_idx2);
    cudaGetSymbolAddress((void**)&p_A,    g_A);
    cudaGetSymbolAddress((void**)&p_B,    g_B);
    cudaGetSymbolAddress((void**)&p_acc,  g_acc);
    cudaGetSymbolAddress((void**)&p_x2,   g_x2);
    cudaGetSymbolAddress((void**)&p_x3,   g_x3);

    const float* nul = nullptr;
    dim3 knn_grid(NPTS / 32, NB);

    /* pre MLP + embed 1 */
    gemm_act<64><<<NN/64, 256>>>(x,     32, nul, 0, W_pre, b_pre, p_xf1, 1);
    gemm_act<64><<<NN/64, 256>>>(p_xf1, 64, nul, 0, W_d1,  b_d1,  p_ge1, 0);

    /* knn 1 + lp 1 */
    sq_kernel<<<NN/256, 256>>>(p_ge1, p_sq);
    knn4_kernel<<<knn_grid, 256>>>(p_ge1, p_sq, p_idx1);
    lp_kernel<<<(NB*NKB)/256, 256>>>(p_ge1, p_idx1, t1, lp, 0);

    /* edge conv 1 */
    gemm_ab<<<NN/64, 256>>>(p_xf1, W_c1, b_c1, p_A, p_B);
    init_acc_kernel<<<(NN*DD)/256, 256>>>(p_acc);
    scatter_kernel<<<(EDGES*16)/256, 256>>>(p_idx1, p_A, p_B, p_acc);
    decode_relu_kernel<<<(NN*DD)/256, 256>>>(p_acc, p_x2);

    /* embed 2 on concat[ge1, x2] */
    gemm_act<64><<<NN/64, 256>>>(p_ge1, 64, p_x2, 64, W_d2, b_d2, p_ge2, 0);

    /* knn 2 + lp 2 */
    sq_kernel<<<NN/256, 256>>>(p_ge2, p_sq);
    knn4_kernel<<<knn_grid, 256>>>(p_ge2, p_sq, p_idx2);
    lp_kernel<<<(NB*NKB)/256, 256>>>(p_ge2, p_idx2, t2, lp, 1);

    /* edge conv 2 */
    gemm_ab<<<NN/64, 256>>>(p_x2, W_c2, b_c2, p_A, p_B);
    init_acc_kernel<<<(NN*DD)/256, 256>>>(p_acc);
    scatter_kernel<<<(EDGES*16)/256, 256>>>(p_idx2, p_A, p_B, p_acc);
    decode_relu_kernel<<<(NN*DD)/256, 256>>>(p_acc, p_x3);

    /* head */
    head_kernel<<<NN/128, 128>>>(p_x3, W_f1, b_f1, W_f2, b_f2, out);
}

// round 6
// speedup vs baseline: 1.1905x; 1.1905x over previous
#include <cuda_runtime.h>
#include <cuda_bf16.h>
#include <float.h>
#include <math.h>

#define NPTS 4096
#define NB 2
#define NN 8192
#define DD 64
#define KK 5
#define NKB (NPTS*KK)      /* 20480 flat (k-major) per batch */
#define EDGES (NB*NKB)     /* 40960 edges */

/* ---------------- scratch (device globals; no allocation allowed) -------- */
__device__ float         g_xf1[NN*DD];
__device__ float         g_ge1[NN*DD];
__device__ float         g_ge2[NN*DD];
__device__ float         g_sq [NN];
__device__ int           g_idx1[NB*NKB];
__device__ int           g_idx2[NB*NKB];
__device__ float         g_A  [NN*DD];
__device__ float         g_B  [NN*DD];
__device__ unsigned      g_acc[NN*DD];
__device__ float         g_x2 [NN*DD];
__device__ float         g_x3 [NN*DD];
__device__ __nv_bfloat16 g_g3 [NN*192];   /* 3-way bf16 split of embeddings */

/* ordered float<->uint key (monotone map, finite floats) */
__device__ __forceinline__ unsigned fkey(float f) {
    unsigned u = __float_as_uint(f);
    return u ^ ((unsigned)(((int)u) >> 31) | 0x80000000u);
}
__device__ __forceinline__ float fdec(unsigned u) {
    unsigned v = u ^ ((u & 0x80000000u) ? 0x80000000u : 0xFFFFFFFFu);
    return __uint_as_float(v);
}
#define NEG_MAX_KEY 0x00800000u   /* fkey(-FLT_MAX) */

/* cp.async helpers */
__device__ __forceinline__ void cp_async16(void* smem_dst, const void* gsrc) {
    unsigned s = (unsigned)__cvta_generic_to_shared(smem_dst);
    asm volatile("cp.async.ca.shared.global [%0], [%1], 16;" :: "r"(s), "l"(gsrc));
}
__device__ __forceinline__ void cp_commit() {
    asm volatile("cp.async.commit_group;" ::: "memory");
}
template<int N> __device__ __forceinline__ void cp_wait() {
    asm volatile("cp.async.wait_group %0;" :: "n"(N) : "memory");
}

/* ldmatrix x4 (b16), shared address precomputed by caller */
__device__ __forceinline__ void ldsm4(unsigned &r0, unsigned &r1, unsigned &r2, unsigned &r3,
                                      unsigned saddr) {
    asm volatile("ldmatrix.sync.aligned.m8n8.x4.shared.b16 {%0,%1,%2,%3}, [%4];"
                 : "=r"(r0), "=r"(r1), "=r"(r2), "=r"(r3) : "r"(saddr));
}

/* mma m16n8k16 row.col f32 <- bf16 x bf16 + f32 */
__device__ __forceinline__ void mma16816(float* c, unsigned a0, unsigned a1,
                                         unsigned a2, unsigned a3,
                                         unsigned b0, unsigned b1) {
    asm volatile("mma.sync.aligned.m16n8k16.row.col.f32.bf16.bf16.f32 "
                 "{%0,%1,%2,%3}, {%4,%5,%6,%7}, {%8,%9}, {%0,%1,%2,%3};"
                 : "+f"(c[0]), "+f"(c[1]), "+f"(c[2]), "+f"(c[3])
                 : "r"(a0), "r"(a1), "r"(a2), "r"(a3), "r"(b0), "r"(b1));
}

/* ---------------- generic small GEMM: Y = act(X@W + b), 64 rows/block ---- */
template<int NCOL>
__global__ __launch_bounds__(256) void gemm_act(
    const float* __restrict__ X1, int k1,
    const float* __restrict__ X2, int k2,
    const float* __restrict__ W, const float* __restrict__ bias,
    float* __restrict__ Y, int act)
{
    constexpr int G  = NCOL / 4;
    constexpr int TY = 256 / G;
    constexpr int R  = 64 / TY;
    __shared__ float Ws[128 * NCOL];
    __shared__ float Xs[64 * 33];
    __shared__ float bs[NCOL];
    const int t = threadIdx.x;
    const int rowBase = blockIdx.x * 64;
    const int KD = k1 + k2;

    for (int f = t; f < KD * NCOL; f += 256) Ws[f] = W[f];
    if (t < NCOL) bs[t] = (bias != nullptr) ? bias[t] : 0.0f;

    const int tx = t % G, ty = t / G;
    float acc[R][4];
#pragma unroll
    for (int rr = 0; rr < R; rr++) { acc[rr][0]=0.f; acc[rr][1]=0.f; acc[rr][2]=0.f; acc[rr][3]=0.f; }

    for (int ko = 0; ko < KD; ko += 32) {
        const float* Xsrc; int stride, koff;
        if (ko < k1) { Xsrc = X1; stride = k1; koff = ko; }
        else         { Xsrc = X2; stride = k2; koff = ko - k1; }
        __syncthreads();
        for (int f = t; f < 64 * 32; f += 256) {
            int r = f >> 5, k = f & 31;
            Xs[r * 33 + k] = Xsrc[(rowBase + r) * stride + koff + k];
        }
        __syncthreads();
#pragma unroll
        for (int k = 0; k < 32; k++) {
            float4 w4 = *(const float4*)(Ws + (ko + k) * NCOL + tx * 4);
#pragma unroll
            for (int rr = 0; rr < R; rr++) {
                float xv = Xs[(ty + rr * TY) * 33 + k];
                acc[rr][0] += xv * w4.x; acc[rr][1] += xv * w4.y;
                acc[rr][2] += xv * w4.z; acc[rr][3] += xv * w4.w;
            }
        }
    }
#pragma unroll
    for (int rr = 0; rr < R; rr++) {
        int r = rowBase + ty + rr * TY;
        float4 o;
        o.x = acc[rr][0] + bs[tx*4+0];
        o.y = acc[rr][1] + bs[tx*4+1];
        o.z = acc[rr][2] + bs[tx*4+2];
        o.w = acc[rr][3] + bs[tx*4+3];
        if (act == 1) {          /* leaky relu 0.1 */
            o.x = o.x > 0.f ? o.x : 0.1f*o.x; o.y = o.y > 0.f ? o.y : 0.1f*o.y;
            o.z = o.z > 0.f ? o.z : 0.1f*o.z; o.w = o.w > 0.f ? o.w : 0.1f*o.w;
        } else if (act == 2) {   /* relu */
            o.x = fmaxf(o.x,0.f); o.y = fmaxf(o.y,0.f);
            o.z = fmaxf(o.z,0.f); o.w = fmaxf(o.w,0.f);
        }
        *(float4*)(Y + r * NCOL + tx * 4) = o;
    }
}

/* -------- fused EdgeConv GEMMs: A = X@(Wtop-Wbot)+bias, B = X@Wbot ------- */
__global__ __launch_bounds__(256) void gemm_ab(
    const float* __restrict__ X, const float* __restrict__ Wc,
    const float* __restrict__ bias, float* __restrict__ A, float* __restrict__ B)
{
    __shared__ float Ws[128 * 64];
    __shared__ float Xs[64 * 33];
    __shared__ float bs[64];
    const int t = threadIdx.x;
    const int rowBase = blockIdx.x * 64;
    for (int f = t; f < 128 * 64; f += 256) Ws[f] = Wc[f];
    if (t < 64) bs[t] = bias[t];

    const int tx = t % 16, ty = t / 16;        /* 16 col-groups x 16 rows */
    float aT[4][4], aB[4][4];
#pragma unroll
    for (int rr = 0; rr < 4; rr++)
#pragma unroll
        for (int c = 0; c < 4; c++) { aT[rr][c] = 0.f; aB[rr][c] = 0.f; }

    for (int ko = 0; ko < 64; ko += 32) {
        __syncthreads();
        for (int f = t; f < 64 * 32; f += 256) {
            int r = f >> 5, k = f & 31;
            Xs[r * 33 + k] = X[(rowBase + r) * 64 + ko + k];
        }
        __syncthreads();
#pragma unroll
        for (int k = 0; k < 32; k++) {
            float4 wt = *(const float4*)(Ws + (ko + k) * 64 + tx * 4);
            float4 wb = *(const float4*)(Ws + (64 + ko + k) * 64 + tx * 4);
#pragma unroll
            for (int rr = 0; rr < 4; rr++) {
                float xv = Xs[(ty + rr * 16) * 33 + k];
                aT[rr][0] = fmaf(xv, wt.x, aT[rr][0]); aT[rr][1] = fmaf(xv, wt.y, aT[rr][1]);
                aT[rr][2] = fmaf(xv, wt.z, aT[rr][2]); aT[rr][3] = fmaf(xv, wt.w, aT[rr][3]);
                aB[rr][0] = fmaf(xv, wb.x, aB[rr][0]); aB[rr][1] = fmaf(xv, wb.y, aB[rr][1]);
                aB[rr][2] = fmaf(xv, wb.z, aB[rr][2]); aB[rr][3] = fmaf(xv, wb.w, aB[rr][3]);
            }
        }
    }
#pragma unroll
    for (int rr = 0; rr < 4; rr++) {
        int r = rowBase + ty + rr * 16;
        float4 ao, bo;
        ao.x = aT[rr][0] - aB[rr][0] + bs[tx*4+0];
        ao.y = aT[rr][1] - aB[rr][1] + bs[tx*4+1];
        ao.z = aT[rr][2] - aB[rr][2] + bs[tx*4+2];
        ao.w = aT[rr][3] - aB[rr][3] + bs[tx*4+3];
        bo.x = aB[rr][0]; bo.y = aB[rr][1]; bo.z = aB[rr][2]; bo.w = aB[rr][3];
        *(float4*)(A + r * 64 + tx * 4) = ao;
        *(float4*)(B + r * 64 + tx * 4) = bo;
    }
}

/* -------- prep: sum of squares + 3-way bf16 split ------------------------ */
__global__ void prep3_kernel(const float* __restrict__ ge,
                             __nv_bfloat16* __restrict__ g3,
                             float* __restrict__ sq)
{
    int i = blockIdx.x * 256 + threadIdx.x;
    if (i >= NN * DD) return;
    int r = i >> 6, d = i & 63;
    float v = ge[i];
    __nv_bfloat16 b0 = __float2bfloat16_rn(v);
    float r1 = v - __bfloat162float(b0);
    __nv_bfloat16 b1 = __float2bfloat16_rn(r1);
    float r2 = r1 - __bfloat162float(b1);
    __nv_bfloat16 b2 = __float2bfloat16_rn(r2);
    __nv_bfloat16* row = g3 + (size_t)r * 192;
    row[d] = b0; row[64 + d] = b1; row[128 + d] = b2;

    if (d == 0) {   /* one thread per row does the sq reduction */
        const float4* p = (const float4*)(ge + r * DD);
        float s0=0.f,s1=0.f,s2=0.f,s3=0.f;
#pragma unroll
        for (int d4 = 0; d4 < 16; d4++) {
            float4 w = p[d4];
            s0 += w.x*w.x; s1 += w.y*w.y; s2 += w.z*w.z; s3 += w.w*w.w;
        }
        sq[r] = (s0+s1)+(s2+s3);
    }
}

/* ---------------- KNN via bf16-split tensor-core GEMM --------------------
   CTA: 64 queries x all 4096 points. 8 warps = 4 m-warps x 2 n-warps.
   Warp tile m16 x n32 per 64-pt tile; K_eff = 6 product pairs x 64 = 384.
   cp.async double-buffered point tiles; ldmatrix operands; reg accum.
   Top-5: per-lane over its 16 dots/tile, then (val,idx)-lex block merge.  */
#define KNN_SMEM 77568
__global__ __launch_bounds__(256, 1) void knn_mma_kernel(
    const __nv_bfloat16* __restrict__ g3, const float* __restrict__ sqg,
    int* __restrict__ idxflat)
{
    extern __shared__ char sm[];
    char*  Qs  = sm;                       /* 64 x 400B            */
    char*  Ps  = sm + 25600;               /* 2 x 64 x 400B        */
    float* sqq = (float*)(sm + 76800);     /* 64                   */
    float* sqp = (float*)(sm + 77056);     /* 2 x 64               */

    const int tid  = threadIdx.x;
    const int lane = tid & 31, w = tid >> 5;
    const int mwarp = w & 3, nwarp = w >> 2;
    const int mbase = mwarp * 16;
    const int qbase = blockIdx.x * 64;
    const int bb    = blockIdx.y;
    const char*  g3b = (const char*)(g3 + (size_t)bb * NPTS * 192);
    const float* sqb = sqg + bb * NPTS;

    /* stage queries: 64 rows x 384B -> stride 400B */
    for (int f = tid; f < 1536; f += 256) {
        int r = f / 24, c = f % 24;
        *(uint4*)(Qs + r * 400 + c * 16) =
            *(const uint4*)(g3b + (size_t)(qbase + r) * 384 + c * 16);
    }
    if (tid < 64) sqq[tid] = sqb[qbase + tid];

    /* prologue: point tile 0 */
    for (int f = tid; f < 1536; f += 256) {
        int r = f / 24, c = f % 24;
        cp_async16(Ps + r * 400 + c * 16, g3b + (size_t)r * 384 + c * 16);
    }
    if (tid < 16) cp_async16((char*)sqp + tid * 16, (const char*)sqb + tid * 16);
    cp_commit();

    /* barrier: sqq/Qs staged by warps 0-1 are read by ALL warps below */
    __syncthreads();

    /* per-lane ldmatrix addresses */
    const unsigned Qs32 = (unsigned)__cvta_generic_to_shared(Qs);
    const unsigned Ps32 = (unsigned)__cvta_generic_to_shared(Ps);
    const int aRow = mbase + ((lane >> 3) & 1) * 8 + (lane & 7);
    const unsigned aAddr = Qs32 + aRow * 400 + ((lane >> 4) & 1) * 16;
    const int bRow = ((lane >> 4) & 1) * 8 + (lane & 7);
    const unsigned bOff = (unsigned)((nwarp * 32 + bRow) * 400 + ((lane >> 3) & 1) * 16);

    float tvA[5], tvB[5]; int tiA[5], tiB[5];
#pragma unroll
    for (int k = 0; k < 5; k++) {
        tvA[k] = FLT_MAX; tiA[k] = 0x7FFFFFFF;
        tvB[k] = FLT_MAX; tiB[k] = 0x7FFFFFFF;
    }
    const float sqiA = sqq[mbase + (lane >> 2)];
    const float sqiB = sqq[mbase + (lane >> 2) + 8];

    const int PA[6] = {0, 0, 1, 0, 2, 1};
    const int PB[6] = {0, 1, 0, 2, 0, 1};

    for (int tt = 0; tt < 64; tt++) {
        if (tt < 63) {
            __syncthreads();            /* compute on buf[(tt+1)&1] finished */
            const char* src = g3b + (size_t)(tt + 1) * 64 * 384;
            char* dst = Ps + ((tt + 1) & 1) * 25600;
            for (int f = tid; f < 1536; f += 256) {
                int r = f / 24, c = f % 24;
                cp_async16(dst + r * 400 + c * 16, src + (size_t)r * 384 + c * 16);
            }
            if (tid < 16) cp_async16((char*)(sqp + ((tt + 1) & 1) * 64) + tid * 16,
                                     (const char*)(sqb + (tt + 1) * 64) + tid * 16);
            cp_commit();
            cp_wait<1>();               /* tile tt landed */
        } else {
            cp_wait<0>();
        }
        __syncthreads();

        const unsigned pbuf = Ps32 + (tt & 1) * 25600;
        const float* SQ = sqp + (tt & 1) * 64;

        float C[4][4];
#pragma unroll
        for (int nb = 0; nb < 4; nb++) {
            C[nb][0] = 0.f; C[nb][1] = 0.f; C[nb][2] = 0.f; C[nb][3] = 0.f;
        }

#pragma unroll
        for (int pr = 0; pr < 6; pr++) {
            const unsigned aB = aAddr + PA[pr] * 128;
            const unsigned bB = pbuf + bOff + PB[pr] * 128;
#pragma unroll
            for (int ks = 0; ks < 4; ks++) {
                unsigned a0, a1, a2, a3, b0, b1, b2, b3, b4, b5, b6, b7;
                ldsm4(a0, a1, a2, a3, aB + ks * 32);
                ldsm4(b0, b1, b2, b3, bB + ks * 32);
                ldsm4(b4, b5, b6, b7, bB + 16 * 400 + ks * 32);
                mma16816(C[0], a0, a1, a2, a3, b0, b1);
                mma16816(C[1], a0, a1, a2, a3, b2, b3);
                mma16816(C[2], a0, a1, a2, a3, b4, b5);
                mma16816(C[3], a0, a1, a2, a3, b6, b7);
            }
        }

        /* epilogue: 16 dots per lane -> distances -> top-5 insert */
#pragma unroll
        for (int nb = 0; nb < 4; nb++) {
            const int col0 = nwarp * 32 + nb * 8 + (lane & 3) * 2;
            const float sp0 = SQ[col0], sp1 = SQ[col0 + 1];
            const int id0 = tt * 64 + col0;
            float d00 = fmaxf(fmaf(-2.f, C[nb][0], sqiA + sp0), 0.f);
            float d01 = fmaxf(fmaf(-2.f, C[nb][1], sqiA + sp1), 0.f);
            float d10 = fmaxf(fmaf(-2.f, C[nb][2], sqiB + sp0), 0.f);
            float d11 = fmaxf(fmaf(-2.f, C[nb][3], sqiB + sp1), 0.f);
#define INS(TV, TI, DV, IDX)                                                   \
            if (DV < TV[4]) {                                                  \
                TV[4] = DV; TI[4] = IDX;                                       \
                _Pragma("unroll")                                              \
                for (int s2 = 4; s2 > 0; s2--) {                               \
                    if (TV[s2] < TV[s2-1]) {                                   \
                        float fv = TV[s2]; TV[s2] = TV[s2-1]; TV[s2-1] = fv;   \
                        int  iv = TI[s2]; TI[s2] = TI[s2-1]; TI[s2-1] = iv;    \
                    }                                                          \
                }                                                              \
            }
            INS(tvA, tiA, d00, id0)
            INS(tvA, tiA, d01, id0 + 1)
            INS(tvB, tiB, d10, id0)
            INS(tvB, tiB, d11, id0 + 1)
#undef INS
        }
    }

    /* block merge: per query 8 lanes x 5 candidates; stride 41 */
    __syncthreads();
    float* cv = (float*)sm;
    int*   ci = (int*)(sm + 64 * 41 * 4);
    {
        const int slot = nwarp * 20 + (lane & 3) * 5;
        const int qA = mbase + (lane >> 2);
#pragma unroll
        for (int k = 0; k < 5; k++) {
            cv[qA * 41 + slot + k] = tvA[k];
            ci[qA * 41 + slot + k] = tiA[k];
            cv[(qA + 8) * 41 + slot + k] = tvB[k];
            ci[(qA + 8) * 41 + slot + k] = tiB[k];
        }
    }
    __syncthreads();
    if (tid < 64) {
        float bv[5]; int bi[5];
#pragma unroll
        for (int k = 0; k < 5; k++) { bv[k] = FLT_MAX; bi[k] = 0x7FFFFFFF; }
        for (int e = 0; e < 40; e++) {
            float v = cv[tid * 41 + e];
            int   i = ci[tid * 41 + e];
            if (v < bv[4] || (v == bv[4] && i < bi[4])) {
                bv[4] = v; bi[4] = i;
#pragma unroll
                for (int s2 = 4; s2 > 0; s2--) {
                    if (bv[s2] < bv[s2-1] || (bv[s2] == bv[s2-1] && bi[s2] < bi[s2-1])) {
                        float fv = bv[s2]; bv[s2] = bv[s2-1]; bv[s2-1] = fv;
                        int  iv = bi[s2]; bi[s2] = bi[s2-1]; bi[s2-1] = iv;
                    }
                }
            }
        }
#pragma unroll
        for (int k = 0; k < 5; k++)
            idxflat[bb * NKB + k * NPTS + qbase + tid] = bi[k];
    }
}

/* ---------------- logprobs: lp[b,i,kk,layer] ----------------------------- */
__global__ void lp_kernel(const float* __restrict__ ge, const int* __restrict__ idxflat,
                          const float* __restrict__ tptr, float* __restrict__ outp, int layer)
{
    int gid = blockIdx.x * blockDim.x + threadIdx.x;
    if (gid >= NB * NKB) return;
    int bb = gid / NKB;
    int m  = gid - bb * NKB;
    float tval = fminf(fmaxf(tptr[0], -5.0f), 5.0f);
    float t = expf(tval);
    int nb  = idxflat[bb * NKB + m];
    int ctr = m / KK;
    int kk  = m - ctr * KK;
    const float4* pa = (const float4*)(ge + (bb * NPTS + nb) * DD);
    const float4* pb = (const float4*)(ge + (bb * NPTS + ctr) * DD);
    float s = 0.f;
#pragma unroll
    for (int d4 = 0; d4 < 16; d4++) {
        float4 a = pa[d4], b4 = pb[d4];
        float dx=a.x-b4.x, dy=a.y-b4.y, dz=a.z-b4.z, dw=a.w-b4.w;
        s += dx*dx + dy*dy + dz*dz + dw*dw;
    }
    outp[((bb * NPTS + ctr) * KK + kk) * 2 + layer] = -s * t;
}

/* ---------------- scatter-max edge conv --------------------------------- */
__global__ void init_acc_kernel(unsigned* __restrict__ acc) {
    int i = blockIdx.x * blockDim.x + threadIdx.x;
    if (i < NN * DD) acc[i] = NEG_MAX_KEY;
}

__global__ void scatter_kernel(const int* __restrict__ idxflat,
                               const float* __restrict__ A, const float* __restrict__ B,
                               unsigned* __restrict__ acc)
{
    int gid = blockIdx.x * blockDim.x + threadIdx.x;
    if (gid >= EDGES * 16) return;
    int q  = gid >> 4;
    int cg = gid & 15;
    int mq = q >> 2;
    int bb = (q >> 1) & 1;
    int c  = q & 1;
    int m_s = mq;
    int m_d = mq + NKB / 2;
    int srcv = (c == 0) ? idxflat[bb * NKB + m_s] : (m_s / KK);
    int dstv = (c == 0) ? idxflat[bb * NKB + m_d] : (m_d / KK);
    srcv += bb * NPTS;
    dstv += bb * NPTS;
    float4 av = ((const float4*)A)[dstv * 16 + cg];
    float4 bv = ((const float4*)B)[srcv * 16 + cg];
    unsigned* base = acc + dstv * DD + cg * 4;
    atomicMax(base + 0, fkey(av.x + bv.x));
    atomicMax(base + 1, fkey(av.y + bv.y));
    atomicMax(base + 2, fkey(av.z + bv.z));
    atomicMax(base + 3, fkey(av.w + bv.w));
}

__global__ void decode_relu_kernel(const unsigned* __restrict__ acc, float* __restrict__ y) {
    int i = blockIdx.x * blockDim.x + threadIdx.x;
    if (i < NN * DD) y[i] = fmaxf(fdec(acc[i]), 0.0f);
}

/* ---------------- fused head: lrelu(x@Wf1+b)@Wf2+b ----------------------- */
__global__ __launch_bounds__(128) void head_kernel(
    const float* __restrict__ x3,
    const float* __restrict__ Wf1, const float* __restrict__ bf1,
    const float* __restrict__ Wf2, const float* __restrict__ bf2,
    float* __restrict__ out)
{
    __shared__ float w1[64 * 32];
    __shared__ float w2[32 * 8];
    __shared__ float b1s[32], b2s[8];
    int t = threadIdx.x;
    for (int f = t; f < 2048; f += 128) w1[f] = Wf1[f];
    for (int f = t; f < 256;  f += 128) w2[f] = Wf2[f];
    if (t < 32) b1s[t] = bf1[t];
    if (t < 8)  b2s[t] = bf2[t];
    __syncthreads();
    int r = blockIdx.x * 128 + t;
    if (r >= NN) return;
    float xr[64];
#pragma unroll
    for (int d4 = 0; d4 < 16; d4++) {
        float4 v = ((const float4*)(x3 + r * DD))[d4];
        xr[d4*4+0]=v.x; xr[d4*4+1]=v.y; xr[d4*4+2]=v.z; xr[d4*4+3]=v.w;
    }
    float o[8];
#pragma unroll
    for (int k = 0; k < 8; k++) o[k] = b2s[k];
    for (int jj = 0; jj < 32; jj++) {
        float h0=0.f,h1=0.f,h2=0.f,h3=0.f;
#pragma unroll
        for (int k = 0; k < 64; k += 4) {
            h0 += xr[k+0] * w1[(k+0)*32 + jj];
            h1 += xr[k+1] * w1[(k+1)*32 + jj];
            h2 += xr[k+2] * w1[(k+2)*32 + jj];
            h3 += xr[k+3] * w1[(k+3)*32 + jj];
        }
        float h = ((h0+h1)+(h2+h3)) + b1s[jj];
        h = h > 0.f ? h : 0.1f * h;
#pragma unroll
        for (int k = 0; k < 8; k++) o[k] += h * w2[jj*8 + k];
    }
#pragma unroll
    for (int k = 0; k < 8; k++) out[r * 8 + k] = o[k];
}

/* ---------------- launch ------------------------------------------------- */
extern "C" void kernel_launch(void* const* d_in, const int* in_sizes, int n_in,
                              void* d_out, int out_size)
{
    const float* x     = (const float*)d_in[0];
    const float* W_pre = (const float*)d_in[1];
    const float* b_pre = (const float*)d_in[2];
    const float* W_d1  = (const float*)d_in[3];
    const float* b_d1  = (const float*)d_in[4];
    const float* t1    = (const float*)d_in[5];
    const float* W_c1  = (const float*)d_in[6];
    const float* b_c1  = (const float*)d_in[7];
    const float* W_d2  = (const float*)d_in[8];
    const float* b_d2  = (const float*)d_in[9];
    const float* t2    = (const float*)d_in[10];
    const float* W_c2  = (const float*)d_in[11];
    const float* b_c2  = (const float*)d_in[12];
    const float* W_f1  = (const float*)d_in[13];
    const float* b_f1  = (const float*)d_in[14];
    const float* W_f2  = (const float*)d_in[15];
    const float* b_f2  = (const float*)d_in[16];

    float* out = (float*)d_out;            /* [2,4096,8] = 65536 floats   */
    float* lp  = out + NN * 8;             /* [2,4096,5,2] = 81920 floats */

    float *p_xf1, *p_ge1, *p_ge2, *p_sq, *p_A, *p_B, *p_x2, *p_x3;
    int *p_idx1, *p_idx2;
    unsigned *p_acc;
    __nv_bfloat16 *p_g3;
    cudaGetSymbolAddress((void**)&p_xf1,  g_xf1);
    cudaGetSymbolAddress((void**)&p_ge1,  g_ge1);
    cudaGetSymbolAddress((void**)&p_ge2,  g_ge2);
    cudaGetSymbolAddress((void**)&p_sq,   g_sq);
    cudaGetSymbolAddress((void**)&p_idx1, g_idx1);
    cudaGetSymbolAddress((void**)&p_idx2, g_idx2);
    cudaGetSymbolAddress((void**)&p_A,    g_A);
    cudaGetSymbolAddress((void**)&p_B,    g_B);
    cudaGetSymbolAddress((void**)&p_acc,  g_acc);
    cudaGetSymbolAddress((void**)&p_x2,   g_x2);
    cudaGetSymbolAddress((void**)&p_x3,   g_x3);
    cudaGetSymbolAddress((void**)&p_g3,   g_g3);

    cudaFuncSetAttribute(knn_mma_kernel, cudaFuncAttributeMaxDynamicSharedMemorySize, KNN_SMEM);

    const float* nul = nullptr;
    dim3 knn_grid(NPTS / 64, NB);

    /* pre MLP + embed 1 */
    gemm_act<64><<<NN/64, 256>>>(x,     32, nul, 0, W_pre, b_pre, p_xf1, 1);
    gemm_act<64><<<NN/64, 256>>>(p_xf1, 64, nul, 0, W_d1,  b_d1,  p_ge1, 0);

    /* knn 1 + lp 1 */
    prep3_kernel<<<(NN*DD)/256, 256>>>(p_ge1, p_g3, p_sq);
    knn_mma_kernel<<<knn_grid, 256, KNN_SMEM>>>(p_g3, p_sq, p_idx1);
    lp_kernel<<<(NB*NKB)/256, 256>>>(p_ge1, p_idx1, t1, lp, 0);

    /* edge conv 1 */
    gemm_ab<<<NN/64, 256>>>(p_xf1, W_c1, b_c1, p_A, p_B);
    init_acc_kernel<<<(NN*DD)/256, 256>>>(p_acc);
    scatter_kernel<<<(EDGES*16)/256, 256>>>(p_idx1, p_A, p_B, p_acc);
    decode_relu_kernel<<<(NN*DD)/256, 256>>>(p_acc, p_x2);

    /* embed 2 on concat[ge1, x2] */
    gemm_act<64><<<NN/64, 256>>>(p_ge1, 64, p_x2, 64, W_d2, b_d2, p_ge2, 0);

    /* knn 2 + lp 2 */
    prep3_kernel<<<(NN*DD)/256, 256>>>(p_ge2, p_g3, p_sq);
    knn_mma_kernel<<<knn_grid, 256, KNN_SMEM>>>(p_g3, p_sq, p_idx2);
    lp_kernel<<<(NB*NKB)/256, 256>>>(p_ge2, p_idx2, t2, lp, 1);

    /* edge conv 2 */
    gemm_ab<<<NN/64, 256>>>(p_x2, W_c2, b_c2, p_A, p_B);
    init_acc_kernel<<<(NN*DD)/256, 256>>>(p_acc);
    scatter_kernel<<<(EDGES*16)/256, 256>>>(p_idx2, p_A, p_B, p_acc);
    decode_relu_kernel<<<(NN*DD)/256, 256>>>(p_acc, p_x3);

    /* head */
    head_kernel<<<NN/128, 128>>>(p_x3, W_f1, b_f1, W_f2, b_f2, out);
}

// round 8
// speedup vs baseline: 1.2297x; 1.0329x over previous
#include <cuda_runtime.h>
#include <cuda_bf16.h>
#include <float.h>
#include <math.h>

#define NPTS 4096
#define NB 2
#define NN 8192
#define DD 64
#define KK 5
#define NKB (NPTS*KK)      /* 20480 flat (k-major) per batch */
#define EDGES (NB*NKB)     /* 40960 edges */

/* ---------------- scratch (device globals; no allocation allowed) -------- */
__device__ float         g_xf1[NN*DD];
__device__ float         g_ge1[NN*DD];
__device__ float         g_ge2[NN*DD];
__device__ float         g_sq [NN];
__device__ int           g_idx1[NB*NKB];
__device__ int           g_idx2[NB*NKB];
__device__ float         g_A  [NN*DD];
__device__ float         g_B  [NN*DD];
__device__ unsigned      g_acc[NN*DD];
__device__ float         g_x2 [NN*DD];
__device__ float         g_x3 [NN*DD];
__device__ __nv_bfloat16 g_g3 [NN*192];   /* 3-way bf16 split of embeddings */

/* ordered float<->uint key (monotone map, finite floats) */
__device__ __forceinline__ unsigned fkey(float f) {
    unsigned u = __float_as_uint(f);
    return u ^ ((unsigned)(((int)u) >> 31) | 0x80000000u);
}
__device__ __forceinline__ float fdec(unsigned u) {
    unsigned v = u ^ ((u & 0x80000000u) ? 0x80000000u : 0xFFFFFFFFu);
    return __uint_as_float(v);
}
#define NEG_MAX_KEY 0x00800000u   /* fkey(-FLT_MAX) */

/* cp.async helpers */
__device__ __forceinline__ void cp_async16(void* smem_dst, const void* gsrc) {
    unsigned s = (unsigned)__cvta_generic_to_shared(smem_dst);
    asm volatile("cp.async.ca.shared.global [%0], [%1], 16;" :: "r"(s), "l"(gsrc));
}
__device__ __forceinline__ void cp_commit() {
    asm volatile("cp.async.commit_group;" ::: "memory");
}
template<int N> __device__ __forceinline__ void cp_wait() {
    asm volatile("cp.async.wait_group %0;" :: "n"(N) : "memory");
}

/* ldmatrix x4 (b16), shared address precomputed by caller */
__device__ __forceinline__ void ldsm4(unsigned &r0, unsigned &r1, unsigned &r2, unsigned &r3,
                                      unsigned saddr) {
    asm volatile("ldmatrix.sync.aligned.m8n8.x4.shared.b16 {%0,%1,%2,%3}, [%4];"
                 : "=r"(r0), "=r"(r1), "=r"(r2), "=r"(r3) : "r"(saddr));
}

/* mma m16n8k16 row.col f32 <- bf16 x bf16 + f32 */
__device__ __forceinline__ void mma16816(float* c, unsigned a0, unsigned a1,
                                         unsigned a2, unsigned a3,
                                         unsigned b0, unsigned b1) {
    asm volatile("mma.sync.aligned.m16n8k16.row.col.f32.bf16.bf16.f32 "
                 "{%0,%1,%2,%3}, {%4,%5,%6,%7}, {%8,%9}, {%0,%1,%2,%3};"
                 : "+f"(c[0]), "+f"(c[1]), "+f"(c[2]), "+f"(c[3])
                 : "r"(a0), "r"(a1), "r"(a2), "r"(a3), "r"(b0), "r"(b1));
}

/* ---------------- generic small GEMM: Y = act(X@W + b), 64 rows/block ---- */
template<int NCOL>
__global__ __launch_bounds__(256) void gemm_act(
    const float* __restrict__ X1, int k1,
    const float* __restrict__ X2, int k2,
    const float* __restrict__ W, const float* __restrict__ bias,
    float* __restrict__ Y, int act)
{
    constexpr int G  = NCOL / 4;
    constexpr int TY = 256 / G;
    constexpr int R  = 64 / TY;
    __shared__ float Ws[128 * NCOL];
    __shared__ float Xs[64 * 33];
    __shared__ float bs[NCOL];
    const int t = threadIdx.x;
    const int rowBase = blockIdx.x * 64;
    const int KD = k1 + k2;

    for (int f = t; f < KD * NCOL; f += 256) Ws[f] = W[f];
    if (t < NCOL) bs[t] = (bias != nullptr) ? bias[t] : 0.0f;

    const int tx = t % G, ty = t / G;
    float acc[R][4];
#pragma unroll
    for (int rr = 0; rr < R; rr++) { acc[rr][0]=0.f; acc[rr][1]=0.f; acc[rr][2]=0.f; acc[rr][3]=0.f; }

    for (int ko = 0; ko < KD; ko += 32) {
        const float* Xsrc; int stride, koff;
        if (ko < k1) { Xsrc = X1; stride = k1; koff = ko; }
        else         { Xsrc = X2; stride = k2; koff = ko - k1; }
        __syncthreads();
        for (int f = t; f < 64 * 32; f += 256) {
            int r = f >> 5, k = f & 31;
            Xs[r * 33 + k] = Xsrc[(rowBase + r) * stride + koff + k];
        }
        __syncthreads();
#pragma unroll
        for (int k = 0; k < 32; k++) {
            float4 w4 = *(const float4*)(Ws + (ko + k) * NCOL + tx * 4);
#pragma unroll
            for (int rr = 0; rr < R; rr++) {
                float xv = Xs[(ty + rr * TY) * 33 + k];
                acc[rr][0] += xv * w4.x; acc[rr][1] += xv * w4.y;
                acc[rr][2] += xv * w4.z; acc[rr][3] += xv * w4.w;
            }
        }
    }
#pragma unroll
    for (int rr = 0; rr < R; rr++) {
        int r = rowBase + ty + rr * TY;
        float4 o;
        o.x = acc[rr][0] + bs[tx*4+0];
        o.y = acc[rr][1] + bs[tx*4+1];
        o.z = acc[rr][2] + bs[tx*4+2];
        o.w = acc[rr][3] + bs[tx*4+3];
        if (act == 1) {          /* leaky relu 0.1 */
            o.x = o.x > 0.f ? o.x : 0.1f*o.x; o.y = o.y > 0.f ? o.y : 0.1f*o.y;
            o.z = o.z > 0.f ? o.z : 0.1f*o.z; o.w = o.w > 0.f ? o.w : 0.1f*o.w;
        } else if (act == 2) {   /* relu */
            o.x = fmaxf(o.x,0.f); o.y = fmaxf(o.y,0.f);
            o.z = fmaxf(o.z,0.f); o.w = fmaxf(o.w,0.f);
        }
        *(float4*)(Y + r * NCOL + tx * 4) = o;
    }
}

/* -------- fused EdgeConv GEMMs: A = X@(Wtop-Wbot)+bias, B = X@Wbot ------- */
__global__ __launch_bounds__(256) void gemm_ab(
    const float* __restrict__ X, const float* __restrict__ Wc,
    const float* __restrict__ bias, float* __restrict__ A, float* __restrict__ B)
{
    __shared__ float Ws[128 * 64];
    __shared__ float Xs[64 * 33];
    __shared__ float bs[64];
    const int t = threadIdx.x;
    const int rowBase = blockIdx.x * 64;
    for (int f = t; f < 128 * 64; f += 256) Ws[f] = Wc[f];
    if (t < 64) bs[t] = bias[t];

    const int tx = t % 16, ty = t / 16;        /* 16 col-groups x 16 rows */
    float aT[4][4], aB[4][4];
#pragma unroll
    for (int rr = 0; rr < 4; rr++)
#pragma unroll
        for (int c = 0; c < 4; c++) { aT[rr][c] = 0.f; aB[rr][c] = 0.f; }

    for (int ko = 0; ko < 64; ko += 32) {
        __syncthreads();
        for (int f = t; f < 64 * 32; f += 256) {
            int r = f >> 5, k = f & 31;
            Xs[r * 33 + k] = X[(rowBase + r) * 64 + ko + k];
        }
        __syncthreads();
#pragma unroll
        for (int k = 0; k < 32; k++) {
            float4 wt = *(const float4*)(Ws + (ko + k) * 64 + tx * 4);
            float4 wb = *(const float4*)(Ws + (64 + ko + k) * 64 + tx * 4);
#pragma unroll
            for (int rr = 0; rr < 4; rr++) {
                float xv = Xs[(ty + rr * 16) * 33 + k];
                aT[rr][0] = fmaf(xv, wt.x, aT[rr][0]); aT[rr][1] = fmaf(xv, wt.y, aT[rr][1]);
                aT[rr][2] = fmaf(xv, wt.z, aT[rr][2]); aT[rr][3] = fmaf(xv, wt.w, aT[rr][3]);
                aB[rr][0] = fmaf(xv, wb.x, aB[rr][0]); aB[rr][1] = fmaf(xv, wb.y, aB[rr][1]);
                aB[rr][2] = fmaf(xv, wb.z, aB[rr][2]); aB[rr][3] = fmaf(xv, wb.w, aB[rr][3]);
            }
        }
    }
#pragma unroll
    for (int rr = 0; rr < 4; rr++) {
        int r = rowBase + ty + rr * 16;
        float4 ao, bo;
        ao.x = aT[rr][0] - aB[rr][0] + bs[tx*4+0];
        ao.y = aT[rr][1] - aB[rr][1] + bs[tx*4+1];
        ao.z = aT[rr][2] - aB[rr][2] + bs[tx*4+2];
        ao.w = aT[rr][3] - aB[rr][3] + bs[tx*4+3];
        bo.x = aB[rr][0]; bo.y = aB[rr][1]; bo.z = aB[rr][2]; bo.w = aB[rr][3];
        *(float4*)(A + r * 64 + tx * 4) = ao;
        *(float4*)(B + r * 64 + tx * 4) = bo;
    }
}

/* -------- prep: sum of squares + 3-way bf16 split ------------------------ */
__global__ void prep3_kernel(const float* __restrict__ ge,
                             __nv_bfloat16* __restrict__ g3,
                             float* __restrict__ sq)
{
    int i = blockIdx.x * 256 + threadIdx.x;
    if (i >= NN * DD) return;
    int r = i >> 6, d = i & 63;
    float v = ge[i];
    __nv_bfloat16 b0 = __float2bfloat16_rn(v);
    float r1 = v - __bfloat162float(b0);
    __nv_bfloat16 b1 = __float2bfloat16_rn(r1);
    float r2 = r1 - __bfloat162float(b1);
    __nv_bfloat16 b2 = __float2bfloat16_rn(r2);
    __nv_bfloat16* row = g3 + (size_t)r * 192;
    row[d] = b0; row[64 + d] = b1; row[128 + d] = b2;

    if (d == 0) {   /* one thread per row does the sq reduction */
        const float4* p = (const float4*)(ge + r * DD);
        float s0=0.f,s1=0.f,s2=0.f,s3=0.f;
#pragma unroll
        for (int d4 = 0; d4 < 16; d4++) {
            float4 w = p[d4];
            s0 += w.x*w.x; s1 += w.y*w.y; s2 += w.z*w.z; s3 += w.w*w.w;
        }
        sq[r] = (s0+s1)+(s2+s3);
    }
}

/* ---------------- KNN via bf16-split tensor-core GEMM --------------------
   CTA: 64 queries x all 4096 points. 8 warps = 4 m-warps x 2 n-warps.
   A-fragments (queries) hoisted to registers (tile-invariant; ldmatrix of
   identical values -> accumulation sequence is BIT-IDENTICAL to the R6
   passing kernel; pair order and single-C-chain order are frozen).        */
#define KNN_SMEM 77568
__global__ __launch_bounds__(256, 1) void knn_mma_kernel(
    const __nv_bfloat16* __restrict__ g3, const float* __restrict__ sqg,
    int* __restrict__ idxflat)
{
    extern __shared__ char sm[];
    char*  Qs  = sm;                       /* 64 x 400B            */
    char*  Ps  = sm + 25600;               /* 2 x 64 x 400B        */
    float* sqq = (float*)(sm + 76800);     /* 64                   */
    float* sqp = (float*)(sm + 77056);     /* 2 x 64               */

    const int tid  = threadIdx.x;
    const int lane = tid & 31, w = tid >> 5;
    const int mwarp = w & 3, nwarp = w >> 2;
    const int mbase = mwarp * 16;
    const int qbase = blockIdx.x * 64;
    const int bb    = blockIdx.y;
    const char*  g3b = (const char*)(g3 + (size_t)bb * NPTS * 192);
    const float* sqb = sqg + bb * NPTS;

    /* stage queries: 64 rows x 384B -> stride 400B */
    for (int f = tid; f < 1536; f += 256) {
        int r = f / 24, c = f % 24;
        *(uint4*)(Qs + r * 400 + c * 16) =
            *(const uint4*)(g3b + (size_t)(qbase + r) * 384 + c * 16);
    }
    if (tid < 64) sqq[tid] = sqb[qbase + tid];

    /* prologue: point tile 0 */
    for (int f = tid; f < 1536; f += 256) {
        int r = f / 24, c = f % 24;
        cp_async16(Ps + r * 400 + c * 16, g3b + (size_t)r * 384 + c * 16);
    }
    if (tid < 16) cp_async16((char*)sqp + tid * 16, (const char*)sqb + tid * 16);
    cp_commit();

    /* barrier: Qs/sqq staged above are read by ALL warps below */
    __syncthreads();

    /* per-lane ldmatrix addresses */
    const unsigned Qs32 = (unsigned)__cvta_generic_to_shared(Qs);
    const unsigned Ps32 = (unsigned)__cvta_generic_to_shared(Ps);
    const int aRow = mbase + ((lane >> 3) & 1) * 8 + (lane & 7);
    const unsigned aAddr = Qs32 + aRow * 400 + ((lane >> 4) & 1) * 16;
    const int bRow = ((lane >> 4) & 1) * 8 + (lane & 7);
    const unsigned bOff = (unsigned)((nwarp * 32 + bRow) * 400 + ((lane >> 3) & 1) * 16);

    /* hoist A fragments: 3 splits x 4 k-steps, tile-invariant */
    unsigned afr[3][4][4];
#pragma unroll
    for (int pa = 0; pa < 3; pa++)
#pragma unroll
        for (int ks = 0; ks < 4; ks++)
            ldsm4(afr[pa][ks][0], afr[pa][ks][1], afr[pa][ks][2], afr[pa][ks][3],
                  aAddr + pa * 128 + ks * 32);

    float tvA[5], tvB[5]; int tiA[5], tiB[5];
#pragma unroll
    for (int k = 0; k < 5; k++) {
        tvA[k] = FLT_MAX; tiA[k] = 0x7FFFFFFF;
        tvB[k] = FLT_MAX; tiB[k] = 0x7FFFFFFF;
    }
    const float sqiA = sqq[mbase + (lane >> 2)];
    const float sqiB = sqq[mbase + (lane >> 2) + 8];

    /* FROZEN pair order (matches R6 passing kernel bit-for-bit) */
    const int PA[6] = {0, 0, 1, 0, 2, 1};
    const int PB[6] = {0, 1, 0, 2, 0, 1};

    for (int tt = 0; tt < 64; tt++) {
        if (tt < 63) {
            __syncthreads();            /* compute on buf[(tt+1)&1] finished */
            const char* src = g3b + (size_t)(tt + 1) * 64 * 384;
            char* dst = Ps + ((tt + 1) & 1) * 25600;
            for (int f = tid; f < 1536; f += 256) {
                int r = f / 24, c = f % 24;
                cp_async16(dst + r * 400 + c * 16, src + (size_t)r * 384 + c * 16);
            }
            if (tid < 16) cp_async16((char*)(sqp + ((tt + 1) & 1) * 64) + tid * 16,
                                     (const char*)(sqb + (tt + 1) * 64) + tid * 16);
            cp_commit();
            cp_wait<1>();               /* tile tt landed */
        } else {
            cp_wait<0>();
        }
        __syncthreads();

        const unsigned bB0 = Ps32 + (tt & 1) * 25600 + bOff;
        const float* SQ = sqp + (tt & 1) * 64;

        float C[4][4];
#pragma unroll
        for (int nb = 0; nb < 4; nb++) {
            C[nb][0] = 0.f; C[nb][1] = 0.f; C[nb][2] = 0.f; C[nb][3] = 0.f;
        }

#pragma unroll
        for (int pr = 0; pr < 6; pr++) {
            const int pa = PA[pr];
            const unsigned bB = bB0 + PB[pr] * 128;
#pragma unroll
            for (int ks = 0; ks < 4; ks++) {
                unsigned b0, b1, b2, b3, b4, b5, b6, b7;
                ldsm4(b0, b1, b2, b3, bB + ks * 32);
                ldsm4(b4, b5, b6, b7, bB + 16 * 400 + ks * 32);
                mma16816(C[0], afr[pa][ks][0], afr[pa][ks][1], afr[pa][ks][2], afr[pa][ks][3], b0, b1);
                mma16816(C[1], afr[pa][ks][0], afr[pa][ks][1], afr[pa][ks][2], afr[pa][ks][3], b2, b3);
                mma16816(C[2], afr[pa][ks][0], afr[pa][ks][1], afr[pa][ks][2], afr[pa][ks][3], b4, b5);
                mma16816(C[3], afr[pa][ks][0], afr[pa][ks][1], afr[pa][ks][2], afr[pa][ks][3], b6, b7);
            }
        }

        /* epilogue: 16 dots per lane -> distances -> top-5 insert */
#pragma unroll
        for (int nb = 0; nb < 4; nb++) {
            const int col0 = nwarp * 32 + nb * 8 + (lane & 3) * 2;
            const float sp0 = SQ[col0], sp1 = SQ[col0 + 1];
            const int id0 = tt * 64 + col0;
            float d00 = fmaxf(fmaf(-2.f, C[nb][0], sqiA + sp0), 0.f);
            float d01 = fmaxf(fmaf(-2.f, C[nb][1], sqiA + sp1), 0.f);
            float d10 = fmaxf(fmaf(-2.f, C[nb][2], sqiB + sp0), 0.f);
            float d11 = fmaxf(fmaf(-2.f, C[nb][3], sqiB + sp1), 0.f);
#define INS(TV, TI, DV, IDX)                                                   \
            if (DV < TV[4]) {                                                  \
                TV[4] = DV; TI[4] = IDX;                                       \
                _Pragma("unroll")                                              \
                for (int s2 = 4; s2 > 0; s2--) {                               \
                    if (TV[s2] < TV[s2-1]) {                                   \
                        float fv = TV[s2]; TV[s2] = TV[s2-1]; TV[s2-1] = fv;   \
                        int  iv = TI[s2]; TI[s2] = TI[s2-1]; TI[s2-1] = iv;    \
                    }                                                          \
                }                                                              \
            }
            INS(tvA, tiA, d00, id0)
            INS(tvA, tiA, d01, id0 + 1)
            INS(tvB, tiB, d10, id0)
            INS(tvB, tiB, d11, id0 + 1)
#undef INS
        }
    }

    /* block merge: per query 8 lanes x 5 candidates; stride 41 */
    __syncthreads();
    float* cv = (float*)sm;
    int*   ci = (int*)(sm + 64 * 41 * 4);
    {
        const int slot = nwarp * 20 + (lane & 3) * 5;
        const int qA = mbase + (lane >> 2);
#pragma unroll
        for (int k = 0; k < 5; k++) {
            cv[qA * 41 + slot + k] = tvA[k];
            ci[qA * 41 + slot + k] = tiA[k];
            cv[(qA + 8) * 41 + slot + k] = tvB[k];
            ci[(qA + 8) * 41 + slot + k] = tiB[k];
        }
    }
    __syncthreads();
    if (tid < 64) {
        float bv[5]; int bi[5];
#pragma unroll
        for (int k = 0; k < 5; k++) { bv[k] = FLT_MAX; bi[k] = 0x7FFFFFFF; }
        for (int e = 0; e < 40; e++) {
            float v = cv[tid * 41 + e];
            int   i = ci[tid * 41 + e];
            if (v < bv[4] || (v == bv[4] && i < bi[4])) {
                bv[4] = v; bi[4] = i;
#pragma unroll
                for (int s2 = 4; s2 > 0; s2--) {
                    if (bv[s2] < bv[s2-1] || (bv[s2] == bv[s2-1] && bi[s2] < bi[s2-1])) {
                        float fv = bv[s2]; bv[s2] = bv[s2-1]; bv[s2-1] = fv;
                        int  iv = bi[s2]; bi[s2] = bi[s2-1]; bi[s2-1] = iv;
                    }
                }
            }
        }
#pragma unroll
        for (int k = 0; k < 5; k++)
            idxflat[bb * NKB + k * NPTS + qbase + tid] = bi[k];
    }
}

/* ---------------- logprobs: lp[b,i,kk,layer] ----------------------------- */
__global__ void lp_kernel(const float* __restrict__ ge, const int* __restrict__ idxflat,
                          const float* __restrict__ tptr, float* __restrict__ outp, int layer)
{
    int gid = blockIdx.x * blockDim.x + threadIdx.x;
    if (gid >= NB * NKB) return;
    int bb = gid / NKB;
    int m  = gid - bb * NKB;
    float tval = fminf(fmaxf(tptr[0], -5.0f), 5.0f);
    float t = expf(tval);
    int nb  = idxflat[bb * NKB + m];
    int ctr = m / KK;
    int kk  = m - ctr * KK;
    const float4* pa = (const float4*)(ge + (bb * NPTS + nb) * DD);
    const float4* pb = (const float4*)(ge + (bb * NPTS + ctr) * DD);
    float s = 0.f;
#pragma unroll
    for (int d4 = 0; d4 < 16; d4++) {
        float4 a = pa[d4], b4 = pb[d4];
        float dx=a.x-b4.x, dy=a.y-b4.y, dz=a.z-b4.z, dw=a.w-b4.w;
        s += dx*dx + dy*dy + dz*dz + dw*dw;
    }
    outp[((bb * NPTS + ctr) * KK + kk) * 2 + layer] = -s * t;
}

/* ---------------- scatter-max edge conv --------------------------------- */
__global__ void init_acc_kernel(unsigned* __restrict__ acc) {
    int i = blockIdx.x * blockDim.x + threadIdx.x;
    if (i < NN * DD) acc[i] = NEG_MAX_KEY;
}

__global__ void scatter_kernel(const int* __restrict__ idxflat,
                               const float* __restrict__ A, const float* __restrict__ B,
                               unsigned* __restrict__ acc)
{
    int gid = blockIdx.x * blockDim.x + threadIdx.x;
    if (gid >= EDGES * 16) return;
    int q  = gid >> 4;
    int cg = gid & 15;
    int mq = q >> 2;
    int bb = (q >> 1) & 1;
    int c  = q & 1;
    int m_s = mq;
    int m_d = mq + NKB / 2;
    int srcv = (c == 0) ? idxflat[bb * NKB + m_s] : (m_s / KK);
    int dstv = (c == 0) ? idxflat[bb * NKB + m_d] : (m_d / KK);
    srcv += bb * NPTS;
    dstv += bb * NPTS;
    float4 av = ((const float4*)A)[dstv * 16 + cg];
    float4 bv = ((const float4*)B)[srcv * 16 + cg];
    unsigned* base = acc + dstv * DD + cg * 4;
    atomicMax(base + 0, fkey(av.x + bv.x));
    atomicMax(base + 1, fkey(av.y + bv.y));
    atomicMax(base + 2, fkey(av.z + bv.z));
    atomicMax(base + 3, fkey(av.w + bv.w));
}

__global__ void decode_relu_kernel(const unsigned* __restrict__ acc, float* __restrict__ y) {
    int i = blockIdx.x * blockDim.x + threadIdx.x;
    if (i < NN * DD) y[i] = fmaxf(fdec(acc[i]), 0.0f);
}

/* ---------------- fused head: lrelu(x@Wf1+b)@Wf2+b ----------------------- */
__global__ __launch_bounds__(128) void head_kernel(
    const float* __restrict__ x3,
    const float* __restrict__ Wf1, const float* __restrict__ bf1,
    const float* __restrict__ Wf2, const float* __restrict__ bf2,
    float* __restrict__ out)
{
    __shared__ float w1[64 * 32];
    __shared__ float w2[32 * 8];
    __shared__ float b1s[32], b2s[8];
    int t = threadIdx.x;
    for (int f = t; f < 2048; f += 128) w1[f] = Wf1[f];
    for (int f = t; f < 256;  f += 128) w2[f] = Wf2[f];
    if (t < 32) b1s[t] = bf1[t];
    if (t < 8)  b2s[t] = bf2[t];
    __syncthreads();
    int r = blockIdx.x * 128 + t;
    if (r >= NN) return;
    float xr[64];
#pragma unroll
    for (int d4 = 0; d4 < 16; d4++) {
        float4 v = ((const float4*)(x3 + r * DD))[d4];
        xr[d4*4+0]=v.x; xr[d4*4+1]=v.y; xr[d4*4+2]=v.z; xr[d4*4+3]=v.w;
    }
    float o[8];
#pragma unroll
    for (int k = 0; k < 8; k++) o[k] = b2s[k];
    for (int jj = 0; jj < 32; jj++) {
        float h0=0.f,h1=0.f,h2=0.f,h3=0.f;
#pragma unroll
        for (int k = 0; k < 64; k += 4) {
            h0 += xr[k+0] * w1[(k+0)*32 + jj];
            h1 += xr[k+1] * w1[(k+1)*32 + jj];
            h2 += xr[k+2] * w1[(k+2)*32 + jj];
            h3 += xr[k+3] * w1[(k+3)*32 + jj];
        }
        float h = ((h0+h1)+(h2+h3)) + b1s[jj];
        h = h > 0.f ? h : 0.1f * h;
#pragma unroll
        for (int k = 0; k < 8; k++) o[k] += h * w2[jj*8 + k];
    }
#pragma unroll
    for (int k = 0; k < 8; k++) out[r * 8 + k] = o[k];
}

/* ---------------- launch ------------------------------------------------- */
extern "C" void kernel_launch(void* const* d_in, const int* in_sizes, int n_in,
                              void* d_out, int out_size)
{
    const float* x     = (const float*)d_in[0];
    const float* W_pre = (const float*)d_in[1];
    const float* b_pre = (const float*)d_in[2];
    const float* W_d1  = (const float*)d_in[3];
    const float* b_d1  = (const float*)d_in[4];
    const float* t1    = (const float*)d_in[5];
    const float* W_c1  = (const float*)d_in[6];
    const float* b_c1  = (const float*)d_in[7];
    const float* W_d2  = (const float*)d_in[8];
    const float* b_d2  = (const float*)d_in[9];
    const float* t2    = (const float*)d_in[10];
    const float* W_c2  = (const float*)d_in[11];
    const float* b_c2  = (const float*)d_in[12];
    const float* W_f1  = (const float*)d_in[13];
    const float* b_f1  = (const float*)d_in[14];
    const float* W_f2  = (const float*)d_in[15];
    const float* b_f2  = (const float*)d_in[16];

    float* out = (float*)d_out;            /* [2,4096,8] = 65536 floats   */
    float* lp  = out + NN * 8;             /* [2,4096,5,2] = 81920 floats */

    float *p_xf1, *p_ge1, *p_ge2, *p_sq, *p_A, *p_B, *p_x2, *p_x3;
    int *p_idx1, *p_idx2;
    unsigned *p_acc;
    __nv_bfloat16 *p_g3;
    cudaGetSymbolAddress((void**)&p_xf1,  g_xf1);
    cudaGetSymbolAddress((void**)&p_ge1,  g_ge1);
    cudaGetSymbolAddress((void**)&p_ge2,  g_ge2);
    cudaGetSymbolAddress((void**)&p_sq,   g_sq);
    cudaGetSymbolAddress((void**)&p_idx1, g_idx1);
    cudaGetSymbolAddress((void**)&p_idx2, g_idx2);
    cudaGetSymbolAddress((void**)&p_A,    g_A);
    cudaGetSymbolAddress((void**)&p_B,    g_B);
    cudaGetSymbolAddress((void**)&p_acc,  g_acc);
    cudaGetSymbolAddress((void**)&p_x2,   g_x2);
    cudaGetSymbolAddress((void**)&p_x3,   g_x3);
    cudaGetSymbolAddress((void**)&p_g3,   g_g3);

    cudaFuncSetAttribute(knn_mma_kernel, cudaFuncAttributeMaxDynamicSharedMemorySize, KNN_SMEM);

    const float* nul = nullptr;
    dim3 knn_grid(NPTS / 64, NB);

    /* pre MLP + embed 1 */
    gemm_act<64><<<NN/64, 256>>>(x,     32, nul, 0, W_pre, b_pre, p_xf1, 1);
    gemm_act<64><<<NN/64, 256>>>(p_xf1, 64, nul, 0, W_d1,  b_d1,  p_ge1, 0);

    /* knn 1 + lp 1 */
    prep3_kernel<<<(NN*DD)/256, 256>>>(p_ge1, p_g3, p_sq);
    knn_mma_kernel<<<knn_grid, 256, KNN_SMEM>>>(p_g3, p_sq, p_idx1);
    lp_kernel<<<(NB*NKB)/256, 256>>>(p_ge1, p_idx1, t1, lp, 0);

    /* edge conv 1 */
    gemm_ab<<<NN/64, 256>>>(p_xf1, W_c1, b_c1, p_A, p_B);
    init_acc_kernel<<<(NN*DD)/256, 256>>>(p_acc);
    scatter_kernel<<<(EDGES*16)/256, 256>>>(p_idx1, p_A, p_B, p_acc);
    decode_relu_kernel<<<(NN*DD)/256, 256>>>(p_acc, p_x2);

    /* embed 2 on concat[ge1, x2] */
    gemm_act<64><<<NN/64, 256>>>(p_ge1, 64, p_x2, 64, W_d2, b_d2, p_ge2, 0);

    /* knn 2 + lp 2 */
    prep3_kernel<<<(NN*DD)/256, 256>>>(p_ge2, p_g3, p_sq);
    knn_mma_kernel<<<knn_grid, 256, KNN_SMEM>>>(p_g3, p_sq, p_idx2);
    lp_kernel<<<(NB*NKB)/256, 256>>>(p_ge2, p_idx2, t2, lp, 1);

    /* edge conv 2 */
    gemm_ab<<<NN/64, 256>>>(p_x2, W_c2, b_c2, p_A, p_B);
    init_acc_kernel<<<(NN*DD)/256, 256>>>(p_acc);
    scatter_kernel<<<(EDGES*16)/256, 256>>>(p_idx2, p_A, p_B, p_acc);
    decode_relu_kernel<<<(NN*DD)/256, 256>>>(p_acc, p_x3);

    /* head */
    head_kernel<<<NN/128, 128>>>(p_x3, W_f1, b_f1, W_f2, b_f2, out);
}

// round 9
// speedup vs baseline: 1.3015x; 1.0584x over previous
#include <cuda_runtime.h>
#include <cuda_bf16.h>
#include <float.h>
#include <math.h>

#define NPTS 4096
#define NB 2
#define NN 8192
#define DD 64
#define KK 5
#define NKB (NPTS*KK)      /* 20480 flat (k-major) per batch */
#define EDGES (NB*NKB)     /* 40960 edges */

/* ---------------- scratch (device globals; no allocation allowed) -------- */
__device__ float         g_xf1[NN*DD];
__device__ float         g_ge1[NN*DD];
__device__ float         g_ge2[NN*DD];
__device__ float         g_sq [NN];
__device__ int           g_idx1[NB*NKB];
__device__ int           g_idx2[NB*NKB];
__device__ float         g_A  [NN*DD];
__device__ float         g_B  [NN*DD];
__device__ unsigned      g_acc[NN*DD];
__device__ float         g_x2 [NN*DD];
__device__ float         g_x3 [NN*DD];
__device__ __nv_bfloat16 g_g3 [NN*192];   /* 3-way bf16 split of embeddings */

/* ordered float<->uint key (monotone map, finite floats) */
__device__ __forceinline__ unsigned fkey(float f) {
    unsigned u = __float_as_uint(f);
    return u ^ ((unsigned)(((int)u) >> 31) | 0x80000000u);
}
__device__ __forceinline__ float fdec(unsigned u) {
    unsigned v = u ^ ((u & 0x80000000u) ? 0x80000000u : 0xFFFFFFFFu);
    return __uint_as_float(v);
}
#define NEG_MAX_KEY 0x00800000u   /* fkey(-FLT_MAX) */

/* cp.async helpers */
__device__ __forceinline__ void cp_async16(void* smem_dst, const void* gsrc) {
    unsigned s = (unsigned)__cvta_generic_to_shared(smem_dst);
    asm volatile("cp.async.ca.shared.global [%0], [%1], 16;" :: "r"(s), "l"(gsrc));
}
__device__ __forceinline__ void cp_commit() {
    asm volatile("cp.async.commit_group;" ::: "memory");
}
template<int N> __device__ __forceinline__ void cp_wait() {
    asm volatile("cp.async.wait_group %0;" :: "n"(N) : "memory");
}

/* ldmatrix x4 (b16), shared address precomputed by caller */
__device__ __forceinline__ void ldsm4(unsigned &r0, unsigned &r1, unsigned &r2, unsigned &r3,
                                      unsigned saddr) {
    asm volatile("ldmatrix.sync.aligned.m8n8.x4.shared.b16 {%0,%1,%2,%3}, [%4];"
                 : "=r"(r0), "=r"(r1), "=r"(r2), "=r"(r3) : "r"(saddr));
}

/* mma m16n8k16 row.col f32 <- bf16 x bf16 + f32 */
__device__ __forceinline__ void mma16816(float* c, unsigned a0, unsigned a1,
                                         unsigned a2, unsigned a3,
                                         unsigned b0, unsigned b1) {
    asm volatile("mma.sync.aligned.m16n8k16.row.col.f32.bf16.bf16.f32 "
                 "{%0,%1,%2,%3}, {%4,%5,%6,%7}, {%8,%9}, {%0,%1,%2,%3};"
                 : "+f"(c[0]), "+f"(c[1]), "+f"(c[2]), "+f"(c[3])
                 : "r"(a0), "r"(a1), "r"(a2), "r"(a3), "r"(b0), "r"(b1));
}

/* ---------------- generic small GEMM: Y = act(X@W + b), 64 rows/block ---- */
template<int NCOL>
__global__ __launch_bounds__(256) void gemm_act(
    const float* __restrict__ X1, int k1,
    const float* __restrict__ X2, int k2,
    const float* __restrict__ W, const float* __restrict__ bias,
    float* __restrict__ Y, int act)
{
    constexpr int G  = NCOL / 4;
    constexpr int TY = 256 / G;
    constexpr int R  = 64 / TY;
    __shared__ float Ws[128 * NCOL];
    __shared__ float Xs[64 * 33];
    __shared__ float bs[NCOL];
    const int t = threadIdx.x;
    const int rowBase = blockIdx.x * 64;
    const int KD = k1 + k2;

    for (int f = t; f < KD * NCOL; f += 256) Ws[f] = W[f];
    if (t < NCOL) bs[t] = (bias != nullptr) ? bias[t] : 0.0f;

    const int tx = t % G, ty = t / G;
    float acc[R][4];
#pragma unroll
    for (int rr = 0; rr < R; rr++) { acc[rr][0]=0.f; acc[rr][1]=0.f; acc[rr][2]=0.f; acc[rr][3]=0.f; }

    for (int ko = 0; ko < KD; ko += 32) {
        const float* Xsrc; int stride, koff;
        if (ko < k1) { Xsrc = X1; stride = k1; koff = ko; }
        else         { Xsrc = X2; stride = k2; koff = ko - k1; }
        __syncthreads();
        for (int f = t; f < 64 * 32; f += 256) {
            int r = f >> 5, k = f & 31;
            Xs[r * 33 + k] = Xsrc[(rowBase + r) * stride + koff + k];
        }
        __syncthreads();
#pragma unroll
        for (int k = 0; k < 32; k++) {
            float4 w4 = *(const float4*)(Ws + (ko + k) * NCOL + tx * 4);
#pragma unroll
            for (int rr = 0; rr < R; rr++) {
                float xv = Xs[(ty + rr * TY) * 33 + k];
                acc[rr][0] += xv * w4.x; acc[rr][1] += xv * w4.y;
                acc[rr][2] += xv * w4.z; acc[rr][3] += xv * w4.w;
            }
        }
    }
#pragma unroll
    for (int rr = 0; rr < R; rr++) {
        int r = rowBase + ty + rr * TY;
        float4 o;
        o.x = acc[rr][0] + bs[tx*4+0];
        o.y = acc[rr][1] + bs[tx*4+1];
        o.z = acc[rr][2] + bs[tx*4+2];
        o.w = acc[rr][3] + bs[tx*4+3];
        if (act == 1) {          /* leaky relu 0.1 */
            o.x = o.x > 0.f ? o.x : 0.1f*o.x; o.y = o.y > 0.f ? o.y : 0.1f*o.y;
            o.z = o.z > 0.f ? o.z : 0.1f*o.z; o.w = o.w > 0.f ? o.w : 0.1f*o.w;
        } else if (act == 2) {   /* relu */
            o.x = fmaxf(o.x,0.f); o.y = fmaxf(o.y,0.f);
            o.z = fmaxf(o.z,0.f); o.w = fmaxf(o.w,0.f);
        }
        *(float4*)(Y + r * NCOL + tx * 4) = o;
    }
}

/* -------- fused EdgeConv GEMMs: A = X@(Wtop-Wbot)+bias, B = X@Wbot ------- */
__global__ __launch_bounds__(256) void gemm_ab(
    const float* __restrict__ X, const float* __restrict__ Wc,
    const float* __restrict__ bias, float* __restrict__ A, float* __restrict__ B)
{
    __shared__ float Ws[128 * 64];
    __shared__ float Xs[64 * 33];
    __shared__ float bs[64];
    const int t = threadIdx.x;
    const int rowBase = blockIdx.x * 64;
    for (int f = t; f < 128 * 64; f += 256) Ws[f] = Wc[f];
    if (t < 64) bs[t] = bias[t];

    const int tx = t % 16, ty = t / 16;        /* 16 col-groups x 16 rows */
    float aT[4][4], aB[4][4];
#pragma unroll
    for (int rr = 0; rr < 4; rr++)
#pragma unroll
        for (int c = 0; c < 4; c++) { aT[rr][c] = 0.f; aB[rr][c] = 0.f; }

    for (int ko = 0; ko < 64; ko += 32) {
        __syncthreads();
        for (int f = t; f < 64 * 32; f += 256) {
            int r = f >> 5, k = f & 31;
            Xs[r * 33 + k] = X[(rowBase + r) * 64 + ko + k];
        }
        __syncthreads();
#pragma unroll
        for (int k = 0; k < 32; k++) {
            float4 wt = *(const float4*)(Ws + (ko + k) * 64 + tx * 4);
            float4 wb = *(const float4*)(Ws + (64 + ko + k) * 64 + tx * 4);
#pragma unroll
            for (int rr = 0; rr < 4; rr++) {
                float xv = Xs[(ty + rr * 16) * 33 + k];
                aT[rr][0] = fmaf(xv, wt.x, aT[rr][0]); aT[rr][1] = fmaf(xv, wt.y, aT[rr][1]);
                aT[rr][2] = fmaf(xv, wt.z, aT[rr][2]); aT[rr][3] = fmaf(xv, wt.w, aT[rr][3]);
                aB[rr][0] = fmaf(xv, wb.x, aB[rr][0]); aB[rr][1] = fmaf(xv, wb.y, aB[rr][1]);
                aB[rr][2] = fmaf(xv, wb.z, aB[rr][2]); aB[rr][3] = fmaf(xv, wb.w, aB[rr][3]);
            }
        }
    }
#pragma unroll
    for (int rr = 0; rr < 4; rr++) {
        int r = rowBase + ty + rr * 16;
        float4 ao, bo;
        ao.x = aT[rr][0] - aB[rr][0] + bs[tx*4+0];
        ao.y = aT[rr][1] - aB[rr][1] + bs[tx*4+1];
        ao.z = aT[rr][2] - aB[rr][2] + bs[tx*4+2];
        ao.w = aT[rr][3] - aB[rr][3] + bs[tx*4+3];
        bo.x = aB[rr][0]; bo.y = aB[rr][1]; bo.z = aB[rr][2]; bo.w = aB[rr][3];
        *(float4*)(A + r * 64 + tx * 4) = ao;
        *(float4*)(B + r * 64 + tx * 4) = bo;
    }
}

/* -------- prep: sum of squares + 3-way bf16 split ------------------------ */
__global__ void prep3_kernel(const float* __restrict__ ge,
                             __nv_bfloat16* __restrict__ g3,
                             float* __restrict__ sq)
{
    int i = blockIdx.x * 256 + threadIdx.x;
    if (i >= NN * DD) return;
    int r = i >> 6, d = i & 63;
    float v = ge[i];
    __nv_bfloat16 b0 = __float2bfloat16_rn(v);
    float r1 = v - __bfloat162float(b0);
    __nv_bfloat16 b1 = __float2bfloat16_rn(r1);
    float r2 = r1 - __bfloat162float(b1);
    __nv_bfloat16 b2 = __float2bfloat16_rn(r2);
    __nv_bfloat16* row = g3 + (size_t)r * 192;
    row[d] = b0; row[64 + d] = b1; row[128 + d] = b2;

    if (d == 0) {   /* one thread per row does the sq reduction */
        const float4* p = (const float4*)(ge + r * DD);
        float s0=0.f,s1=0.f,s2=0.f,s3=0.f;
#pragma unroll
        for (int d4 = 0; d4 < 16; d4++) {
            float4 w = p[d4];
            s0 += w.x*w.x; s1 += w.y*w.y; s2 += w.z*w.z; s3 += w.w*w.w;
        }
        sq[r] = (s0+s1)+(s2+s3);
    }
}

/* ---------------- KNN via bf16-split tensor-core GEMM --------------------
   CTA: 64 queries x all 4096 points. 16 warps = 4 m-warps x 4 n-warps
   (each n-warp owns 16 point-cols -> 4 warps/SMSP for latency hiding).
   Accumulation sequence per output element is BIT-IDENTICAL to the R6/R8
   passing kernels (same PA/PB order, same ks order, same HMMA).
   Top-5 selection is partition-invariant: ascending-index scan per lane +
   (val,idx)-lexicographic merge = global lexicographic top-5.             */
#define KNN_SMEM 77568
__global__ __launch_bounds__(512, 1) void knn_mma_kernel(
    const __nv_bfloat16* __restrict__ g3, const float* __restrict__ sqg,
    int* __restrict__ idxflat)
{
    extern __shared__ char sm[];
    char*  Qs  = sm;                       /* 64 x 400B            */
    char*  Ps  = sm + 25600;               /* 2 x 64 x 400B        */
    float* sqq = (float*)(sm + 76800);     /* 64                   */
    float* sqp = (float*)(sm + 77056);     /* 2 x 64               */

    const int tid  = threadIdx.x;
    const int lane = tid & 31, w = tid >> 5;
    const int mwarp = w & 3, nwarp = w >> 2;     /* 4 x 4 */
    const int mbase = mwarp * 16;
    const int qbase = blockIdx.x * 64;
    const int bb    = blockIdx.y;
    const char*  g3b = (const char*)(g3 + (size_t)bb * NPTS * 192);
    const float* sqb = sqg + bb * NPTS;

    /* stage queries: 64 rows x 384B -> stride 400B */
    for (int f = tid; f < 1536; f += 512) {
        int r = f / 24, c = f % 24;
        *(uint4*)(Qs + r * 400 + c * 16) =
            *(const uint4*)(g3b + (size_t)(qbase + r) * 384 + c * 16);
    }
    if (tid < 64) sqq[tid] = sqb[qbase + tid];

    /* prologue: point tile 0 */
    for (int f = tid; f < 1536; f += 512) {
        int r = f / 24, c = f % 24;
        cp_async16(Ps + r * 400 + c * 16, g3b + (size_t)r * 384 + c * 16);
    }
    if (tid < 16) cp_async16((char*)sqp + tid * 16, (const char*)sqb + tid * 16);
    cp_commit();

    /* barrier: Qs/sqq staged above are read by ALL warps below */
    __syncthreads();

    /* per-lane ldmatrix addresses */
    const unsigned Qs32 = (unsigned)__cvta_generic_to_shared(Qs);
    const unsigned Ps32 = (unsigned)__cvta_generic_to_shared(Ps);
    const int aRow = mbase + ((lane >> 3) & 1) * 8 + (lane & 7);
    const unsigned aAddr = Qs32 + aRow * 400 + ((lane >> 4) & 1) * 16;
    const int bRow = ((lane >> 4) & 1) * 8 + (lane & 7);
    const unsigned bOff = (unsigned)((nwarp * 16 + bRow) * 400 + ((lane >> 3) & 1) * 16);

    /* hoist A fragments: 3 splits x 4 k-steps, tile-invariant */
    unsigned afr[3][4][4];
#pragma unroll
    for (int pa = 0; pa < 3; pa++)
#pragma unroll
        for (int ks = 0; ks < 4; ks++)
            ldsm4(afr[pa][ks][0], afr[pa][ks][1], afr[pa][ks][2], afr[pa][ks][3],
                  aAddr + pa * 128 + ks * 32);

    float tvA[5], tvB[5]; int tiA[5], tiB[5];
#pragma unroll
    for (int k = 0; k < 5; k++) {
        tvA[k] = FLT_MAX; tiA[k] = 0x7FFFFFFF;
        tvB[k] = FLT_MAX; tiB[k] = 0x7FFFFFFF;
    }
    const float sqiA = sqq[mbase + (lane >> 2)];
    const float sqiB = sqq[mbase + (lane >> 2) + 8];

    /* FROZEN pair order (matches R6/R8 passing kernels bit-for-bit) */
    const int PA[6] = {0, 0, 1, 0, 2, 1};
    const int PB[6] = {0, 1, 0, 2, 0, 1};

    for (int tt = 0; tt < 64; tt++) {
        if (tt < 63) {
            __syncthreads();            /* compute on buf[(tt+1)&1] finished */
            const char* src = g3b + (size_t)(tt + 1) * 64 * 384;
            char* dst = Ps + ((tt + 1) & 1) * 25600;
            for (int f = tid; f < 1536; f += 512) {
                int r = f / 24, c = f % 24;
                cp_async16(dst + r * 400 + c * 16, src + (size_t)r * 384 + c * 16);
            }
            if (tid < 16) cp_async16((char*)(sqp + ((tt + 1) & 1) * 64) + tid * 16,
                                     (const char*)(sqb + (tt + 1) * 64) + tid * 16);
            cp_commit();
            cp_wait<1>();               /* tile tt landed */
        } else {
            cp_wait<0>();
        }
        __syncthreads();

        const unsigned bB0 = Ps32 + (tt & 1) * 25600 + bOff;
        const float* SQ = sqp + (tt & 1) * 64;

        float C[2][4];
        C[0][0]=0.f; C[0][1]=0.f; C[0][2]=0.f; C[0][3]=0.f;
        C[1][0]=0.f; C[1][1]=0.f; C[1][2]=0.f; C[1][3]=0.f;

#pragma unroll
        for (int pr = 0; pr < 6; pr++) {
            const int pa = PA[pr];
            const unsigned bB = bB0 + PB[pr] * 128;
#pragma unroll
            for (int ks = 0; ks < 4; ks++) {
                unsigned b0, b1, b2, b3;
                ldsm4(b0, b1, b2, b3, bB + ks * 32);
                mma16816(C[0], afr[pa][ks][0], afr[pa][ks][1], afr[pa][ks][2], afr[pa][ks][3], b0, b1);
                mma16816(C[1], afr[pa][ks][0], afr[pa][ks][1], afr[pa][ks][2], afr[pa][ks][3], b2, b3);
            }
        }

        /* epilogue: 8 dots per lane -> distances -> top-5 insert */
#pragma unroll
        for (int nb = 0; nb < 2; nb++) {
            const int col0 = nwarp * 16 + nb * 8 + (lane & 3) * 2;
            const float sp0 = SQ[col0], sp1 = SQ[col0 + 1];
            const int id0 = tt * 64 + col0;
            float d00 = fmaxf(fmaf(-2.f, C[nb][0], sqiA + sp0), 0.f);
            float d01 = fmaxf(fmaf(-2.f, C[nb][1], sqiA + sp1), 0.f);
            float d10 = fmaxf(fmaf(-2.f, C[nb][2], sqiB + sp0), 0.f);
            float d11 = fmaxf(fmaf(-2.f, C[nb][3], sqiB + sp1), 0.f);
#define INS(TV, TI, DV, IDX)                                                   \
            if (DV < TV[4]) {                                                  \
                TV[4] = DV; TI[4] = IDX;                                       \
                _Pragma("unroll")                                              \
                for (int s2 = 4; s2 > 0; s2--) {                               \
                    if (TV[s2] < TV[s2-1]) {                                   \
                        float fv = TV[s2]; TV[s2] = TV[s2-1]; TV[s2-1] = fv;   \
                        int  iv = TI[s2]; TI[s2] = TI[s2-1]; TI[s2-1] = iv;    \
                    }                                                          \
                }                                                              \
            }
            INS(tvA, tiA, d00, id0)
            INS(tvA, tiA, d01, id0 + 1)
            INS(tvB, tiB, d10, id0)
            INS(tvB, tiB, d11, id0 + 1)
#undef INS
        }
    }

    /* block merge: per query 16 lanes x 5 candidates; stride 81 */
    __syncthreads();
    float* cv = (float*)sm;
    int*   ci = (int*)(sm + 64 * 81 * 4);
    {
        const int slot = nwarp * 20 + (lane & 3) * 5;
        const int qA = mbase + (lane >> 2);
#pragma unroll
        for (int k = 0; k < 5; k++) {
            cv[qA * 81 + slot + k] = tvA[k];
            ci[qA * 81 + slot + k] = tiA[k];
            cv[(qA + 8) * 81 + slot + k] = tvB[k];
            ci[(qA + 8) * 81 + slot + k] = tiB[k];
        }
    }
    __syncthreads();
    if (tid < 64) {
        float bv[5]; int bi[5];
#pragma unroll
        for (int k = 0; k < 5; k++) { bv[k] = FLT_MAX; bi[k] = 0x7FFFFFFF; }
        for (int e = 0; e < 80; e++) {
            float v = cv[tid * 81 + e];
            int   i = ci[tid * 81 + e];
            if (v < bv[4] || (v == bv[4] && i < bi[4])) {
                bv[4] = v; bi[4] = i;
#pragma unroll
                for (int s2 = 4; s2 > 0; s2--) {
                    if (bv[s2] < bv[s2-1] || (bv[s2] == bv[s2-1] && bi[s2] < bi[s2-1])) {
                        float fv = bv[s2]; bv[s2] = bv[s2-1]; bv[s2-1] = fv;
                        int  iv = bi[s2]; bi[s2] = bi[s2-1]; bi[s2-1] = iv;
                    }
                }
            }
        }
#pragma unroll
        for (int k = 0; k < 5; k++)
            idxflat[bb * NKB + k * NPTS + qbase + tid] = bi[k];
    }
}

/* ---------------- logprobs: lp[b,i,kk,layer] ----------------------------- */
__global__ void lp_kernel(const float* __restrict__ ge, const int* __restrict__ idxflat,
                          const float* __restrict__ tptr, float* __restrict__ outp, int layer)
{
    int gid = blockIdx.x * blockDim.x + threadIdx.x;
    if (gid >= NB * NKB) return;
    int bb = gid / NKB;
    int m  = gid - bb * NKB;
    float tval = fminf(fmaxf(tptr[0], -5.0f), 5.0f);
    float t = expf(tval);
    int nb  = idxflat[bb * NKB + m];
    int ctr = m / KK;
    int kk  = m - ctr * KK;
    const float4* pa = (const float4*)(ge + (bb * NPTS + nb) * DD);
    const float4* pb = (const float4*)(ge + (bb * NPTS + ctr) * DD);
    float s = 0.f;
#pragma unroll
    for (int d4 = 0; d4 < 16; d4++) {
        float4 a = pa[d4], b4 = pb[d4];
        float dx=a.x-b4.x, dy=a.y-b4.y, dz=a.z-b4.z, dw=a.w-b4.w;
        s += dx*dx + dy*dy + dz*dz + dw*dw;
    }
    outp[((bb * NPTS + ctr) * KK + kk) * 2 + layer] = -s * t;
}

/* ---------------- scatter-max edge conv --------------------------------- */
__global__ void init_acc_kernel(unsigned* __restrict__ acc) {
    int i = blockIdx.x * blockDim.x + threadIdx.x;
    if (i < NN * DD) acc[i] = NEG_MAX_KEY;
}

__global__ void scatter_kernel(const int* __restrict__ idxflat,
                               const float* __restrict__ A, const float* __restrict__ B,
                               unsigned* __restrict__ acc)
{
    int gid = blockIdx.x * blockDim.x + threadIdx.x;
    if (gid >= EDGES * 16) return;
    int q  = gid >> 4;
    int cg = gid & 15;
    int mq = q >> 2;
    int bb = (q >> 1) & 1;
    int c  = q & 1;
    int m_s = mq;
    int m_d = mq + NKB / 2;
    int srcv = (c == 0) ? idxflat[bb * NKB + m_s] : (m_s / KK);
    int dstv = (c == 0) ? idxflat[bb * NKB + m_d] : (m_d / KK);
    srcv += bb * NPTS;
    dstv += bb * NPTS;
    float4 av = ((const float4*)A)[dstv * 16 + cg];
    float4 bv = ((const float4*)B)[srcv * 16 + cg];
    unsigned* base = acc + dstv * DD + cg * 4;
    atomicMax(base + 0, fkey(av.x + bv.x));
    atomicMax(base + 1, fkey(av.y + bv.y));
    atomicMax(base + 2, fkey(av.z + bv.z));
    atomicMax(base + 3, fkey(av.w + bv.w));
}

__global__ void decode_relu_kernel(const unsigned* __restrict__ acc, float* __restrict__ y) {
    int i = blockIdx.x * blockDim.x + threadIdx.x;
    if (i < NN * DD) y[i] = fmaxf(fdec(acc[i]), 0.0f);
}

/* ---------------- fused head: lrelu(x@Wf1+b)@Wf2+b ----------------------- */
__global__ __launch_bounds__(128) void head_kernel(
    const float* __restrict__ x3,
    const float* __restrict__ Wf1, const float* __restrict__ bf1,
    const float* __restrict__ Wf2, const float* __restrict__ bf2,
    float* __restrict__ out)
{
    __shared__ float w1[64 * 32];
    __shared__ float w2[32 * 8];
    __shared__ float b1s[32], b2s[8];
    int t = threadIdx.x;
    for (int f = t; f < 2048; f += 128) w1[f] = Wf1[f];
    for (int f = t; f < 256;  f += 128) w2[f] = Wf2[f];
    if (t < 32) b1s[t] = bf1[t];
    if (t < 8)  b2s[t] = bf2[t];
    __syncthreads();
    int r = blockIdx.x * 128 + t;
    if (r >= NN) return;
    float xr[64];
#pragma unroll
    for (int d4 = 0; d4 < 16; d4++) {
        float4 v = ((const float4*)(x3 + r * DD))[d4];
        xr[d4*4+0]=v.x; xr[d4*4+1]=v.y; xr[d4*4+2]=v.z; xr[d4*4+3]=v.w;
    }
    float o[8];
#pragma unroll
    for (int k = 0; k < 8; k++) o[k] = b2s[k];
    for (int jj = 0; jj < 32; jj++) {
        float h0=0.f,h1=0.f,h2=0.f,h3=0.f;
#pragma unroll
        for (int k = 0; k < 64; k += 4) {
            h0 += xr[k+0] * w1[(k+0)*32 + jj];
            h1 += xr[k+1] * w1[(k+1)*32 + jj];
            h2 += xr[k+2] * w1[(k+2)*32 + jj];
            h3 += xr[k+3] * w1[(k+3)*32 + jj];
        }
        float h = ((h0+h1)+(h2+h3)) + b1s[jj];
        h = h > 0.f ? h : 0.1f * h;
#pragma unroll
        for (int k = 0; k < 8; k++) o[k] += h * w2[jj*8 + k];
    }
#pragma unroll
    for (int k = 0; k < 8; k++) out[r * 8 + k] = o[k];
}

/* ---------------- launch ------------------------------------------------- */
extern "C" void kernel_launch(void* const* d_in, const int* in_sizes, int n_in,
                              void* d_out, int out_size)
{
    const float* x     = (const float*)d_in[0];
    const float* W_pre = (const float*)d_in[1];
    const float* b_pre = (const float*)d_in[2];
    const float* W_d1  = (const float*)d_in[3];
    const float* b_d1  = (const float*)d_in[4];
    const float* t1    = (const float*)d_in[5];
    const float* W_c1  = (const float*)d_in[6];
    const float* b_c1  = (const float*)d_in[7];
    const float* W_d2  = (const float*)d_in[8];
    const float* b_d2  = (const float*)d_in[9];
    const float* t2    = (const float*)d_in[10];
    const float* W_c2  = (const float*)d_in[11];
    const float* b_c2  = (const float*)d_in[12];
    const float* W_f1  = (const float*)d_in[13];
    const float* b_f1  = (const float*)d_in[14];
    const float* W_f2  = (const float*)d_in[15];
    const float* b_f2  = (const float*)d_in[16];

    float* out = (float*)d_out;            /* [2,4096,8] = 65536 floats   */
    float* lp  = out + NN * 8;             /* [2,4096,5,2] = 81920 floats */

    float *p_xf1, *p_ge1, *p_ge2, *p_sq, *p_A, *p_B, *p_x2, *p_x3;
    int *p_idx1, *p_idx2;
    unsigned *p_acc;
    __nv_bfloat16 *p_g3;
    cudaGetSymbolAddress((void**)&p_xf1,  g_xf1);
    cudaGetSymbolAddress((void**)&p_ge1,  g_ge1);
    cudaGetSymbolAddress((void**)&p_ge2,  g_ge2);
    cudaGetSymbolAddress((void**)&p_sq,   g_sq);
    cudaGetSymbolAddress((void**)&p_idx1, g_idx1);
    cudaGetSymbolAddress((void**)&p_idx2, g_idx2);
    cudaGetSymbolAddress((void**)&p_A,    g_A);
    cudaGetSymbolAddress((void**)&p_B,    g_B);
    cudaGetSymbolAddress((void**)&p_acc,  g_acc);
    cudaGetSymbolAddress((void**)&p_x2,   g_x2);
    cudaGetSymbolAddress((void**)&p_x3,   g_x3);
    cudaGetSymbolAddress((void**)&p_g3,   g_g3);

    cudaFuncSetAttribute(knn_mma_kernel, cudaFuncAttributeMaxDynamicSharedMemorySize, KNN_SMEM);

    const float* nul = nullptr;
    dim3 knn_grid(NPTS / 64, NB);

    /* pre MLP + embed 1 */
    gemm_act<64><<<NN/64, 256>>>(x,     32, nul, 0, W_pre, b_pre, p_xf1, 1);
    gemm_act<64><<<NN/64, 256>>>(p_xf1, 64, nul, 0, W_d1,  b_d1,  p_ge1, 0);

    /* knn 1 + lp 1 */
    prep3_kernel<<<(NN*DD)/256, 256>>>(p_ge1, p_g3, p_sq);
    knn_mma_kernel<<<knn_grid, 512, KNN_SMEM>>>(p_g3, p_sq, p_idx1);
    lp_kernel<<<(NB*NKB)/256, 256>>>(p_ge1, p_idx1, t1, lp, 0);

    /* edge conv 1 */
    gemm_ab<<<NN/64, 256>>>(p_xf1, W_c1, b_c1, p_A, p_B);
    init_acc_kernel<<<(NN*DD)/256, 256>>>(p_acc);
    scatter_kernel<<<(EDGES*16)/256, 256>>>(p_idx1, p_A, p_B, p_acc);
    decode_relu_kernel<<<(NN*DD)/256, 256>>>(p_acc, p_x2);

    /* embed 2 on concat[ge1, x2] */
    gemm_act<64><<<NN/64, 256>>>(p_ge1, 64, p_x2, 64, W_d2, b_d2, p_ge2, 0);

    /* knn 2 + lp 2 */
    prep3_kernel<<<(NN*DD)/256, 256>>>(p_ge2, p_g3, p_sq);
    knn_mma_kernel<<<knn_grid, 512, KNN_SMEM>>>(p_g3, p_sq, p_idx2);
    lp_kernel<<<(NB*NKB)/256, 256>>>(p_ge2, p_idx2, t2, lp, 1);

    /* edge conv 2 */
    gemm_ab<<<NN/64, 256>>>(p_x2, W_c2, b_c2, p_A, p_B);
    init_acc_kernel<<<(NN*DD)/256, 256>>>(p_acc);
    scatter_kernel<<<(EDGES*16)/256, 256>>>(p_idx2, p_A, p_B, p_acc);
    decode_relu_kernel<<<(NN*DD)/256, 256>>>(p_acc, p_x3);

    /* head */
    head_kernel<<<NN/128, 128>>>(p_x3, W_f1, b_f1, W_f2, b_f2, out);
}